// round 13
// baseline (speedup 1.0000x reference)
#include <cuda_runtime.h>
#include <cuda_bf16.h>
#include <cuda_fp16.h>
#include <cstdint>
#include <math.h>

#define S_TOK 2048
#define EMB   1152
#define NH    16
#define HD    72
#define KDIM  1152
#define BK    32
#define NCHUNK (KDIM / BK)          // 36

// ---- fp16 1-term GEMM, BN=64 (oproj): 3-stage ----
#define P_A 0
#define P_B 10240
#define P_STAGE 15360
#define PRJ_SMEM (3 * P_STAGE)      // 46080

// ---- fp16 1-term GEMM, BN=128 (qkv): 3-stage ----
#define Q_A 0
#define Q_B 10240
#define Q_STAGE 20480
#define QKV_SMEM (3 * Q_STAGE)      // 61440

// ---- attention smem: Q fp16 hi/lo + 3 KV stages (K fp16, V fp16) ----
#define A_ROWB 176
#define AQ_H 0
#define AQ_L 22528
#define AKV0 45056
#define KO   0
#define VO   5632
#define KVS  11264
#define ATTN_SMEM (45056 + 3 * KVS)   // 78848

// ---------------- scratch ----------------------------------------------------
__device__ float g_q[S_TOK * EMB];
__device__ float g_k[S_TOK * EMB];

__device__ __align__(16) __half g_q_hi[S_TOK * EMB];
__device__ __align__(16) __half g_q_lo[S_TOK * EMB];
__device__ __align__(16) __half g_k_16[S_TOK * EMB];
__device__ __align__(16) __half g_v_16[S_TOK * EMB];
__device__ __align__(16) __half g_hs16[S_TOK * EMB];
__device__ __align__(16) __half g_a16 [S_TOK * EMB];
__device__ __align__(16) __half g_w16 [4][EMB * EMB];

// ---------------- helpers ----------------------------------------------------
__device__ __forceinline__ uint32_t smem_u32(const void* p) {
    uint32_t a;
    asm("{ .reg .u64 t; cvta.to.shared.u64 t, %1; cvt.u32.u64 %0, t; }"
        : "=r"(a) : "l"(p));
    return a;
}

#define CP_ASYNC16(dst, src) \
    asm volatile("cp.async.cg.shared.global [%0], [%1], 16;" :: "r"(dst), "l"(src))
#define CP_COMMIT() asm volatile("cp.async.commit_group;" ::: "memory")
#define CP_WAIT(n)  asm volatile("cp.async.wait_group %0;" :: "n"(n) : "memory")

#define LDSM_X4(r, addr) \
    asm volatile("ldmatrix.sync.aligned.m8n8.x4.shared.b16 {%0,%1,%2,%3}, [%4];" \
        : "=r"((r)[0]), "=r"((r)[1]), "=r"((r)[2]), "=r"((r)[3]) : "r"(addr))
#define LDSM_X4_T(r, addr) \
    asm volatile("ldmatrix.sync.aligned.m8n8.x4.trans.shared.b16 {%0,%1,%2,%3}, [%4];" \
        : "=r"((r)[0]), "=r"((r)[1]), "=r"((r)[2]), "=r"((r)[3]) : "r"(addr))

#define MMA16816H(d, a, b0, b1) \
    asm volatile("mma.sync.aligned.m16n8k16.row.col.f32.f16.f16.f32 " \
        "{%0,%1,%2,%3}, {%4,%5,%6,%7}, {%8,%9}, {%0,%1,%2,%3};" \
        : "+f"((d)[0]), "+f"((d)[1]), "+f"((d)[2]), "+f"((d)[3]) \
        : "r"((a)[0]), "r"((a)[1]), "r"((a)[2]), "r"((a)[3]), "r"(b0), "r"(b1))

__device__ __forceinline__ uint32_t pk2h(float lo, float hi) {
    uint32_t r;
    asm("cvt.rn.f16x2.f32 %0, %1, %2;" : "=r"(r) : "f"(hi), "f"(lo));
    return r;
}
__device__ __forceinline__ float f2h(float x) {
    return __half2float(__float2half(x));
}

// ---------------------------------------------------------------------------
// qkv: fp16 1-term GEMM, BM=128, BN=128, BK=32, 3-stage, occ 2.
// 8 warps: wm = w&3 (32-row blocks), wn = w>>2 (64-col blocks).
// z selects weight/bias/output (Q,K fp32; V fp16).
// ---------------------------------------------------------------------------
__global__ __launch_bounds__(256, 2) void qkv_f16_kernel(
    const __half* __restrict__ hs16, const __half* __restrict__ w16,
    const float* __restrict__ qb, const float* __restrict__ kb,
    const float* __restrict__ vb,
    float* __restrict__ Cq, float* __restrict__ Ck, __half* __restrict__ V16)
{
    extern __shared__ __align__(16) char smem[];
    const uint32_t sbase = smem_u32(smem);

    const __half* A = hs16;
    const __half* W = w16 + (size_t)blockIdx.z * EMB * EMB;
    const float* bias;
    float* C = nullptr;
    __half* C16 = nullptr;
    if (blockIdx.z == 0)      { bias = qb; C = Cq; }
    else if (blockIdx.z == 1) { bias = kb; C = Ck; }
    else                      { bias = vb; C16 = V16; }

    const int tid  = threadIdx.x;
    const int lane = tid & 31;
    const int w    = tid >> 5;
    const int wm   = w & 3;             // 4 m-blocks of 32
    const int wn   = w >> 2;            // 2 n-blocks of 64
    const int rBase = blockIdx.y * 128;
    const int cBase = blockIdx.x * 128;

    const int j  = lane >> 3;
    const int l8 = lane & 7;
    const uint32_t a_lane_off =
        (uint32_t)((wm * 32 + (j & 1) * 8 + l8) * 80 + (j >> 1) * 16);
    const uint32_t b_lane_off =
        (uint32_t)((wn * 64 + (j >> 1) * 8 + l8) * 80 + (j & 1) * 16);

    float acc[2][8][4];
#pragma unroll
    for (int mt = 0; mt < 2; mt++)
#pragma unroll
        for (int nt = 0; nt < 8; nt++)
#pragma unroll
            for (int e = 0; e < 4; e++) acc[mt][nt][e] = 0.f;

    auto load_stage = [&](int s, int kc) {
        const uint32_t dst0 = sbase + s * Q_STAGE;
        const int r = tid >> 1, c0 = (tid & 1) * 2;
        {
            const size_t g = (size_t)(rBase + r) * KDIM + kc + c0 * 8;
            const uint32_t d = dst0 + Q_A + r * 80 + c0 * 16;
            CP_ASYNC16(d,      A + g);
            CP_ASYNC16(d + 16, A + g + 8);
        }
        {
            const size_t g = (size_t)(cBase + r) * KDIM + kc + c0 * 8;
            const uint32_t d = dst0 + Q_B + r * 80 + c0 * 16;
            CP_ASYNC16(d,      W + g);
            CP_ASYNC16(d + 16, W + g + 8);
        }
    };

    load_stage(0, 0); CP_COMMIT();
    load_stage(1, BK); CP_COMMIT();

    for (int i = 0; i < NCHUNK; i++) {
        if (i + 1 < NCHUNK) { CP_WAIT(1); } else { CP_WAIT(0); }
        __syncthreads();
        if (i + 2 < NCHUNK) {
            load_stage((i + 2) % 3, (i + 2) * BK);
            CP_COMMIT();
        }

        const uint32_t base = sbase + (i % 3) * Q_STAGE;
#pragma unroll
        for (int ks = 0; ks < 2; ks++) {
            const uint32_t koff = ks * 32;
            uint32_t bh[4][4];
#pragma unroll
            for (int p = 0; p < 4; p++)
                LDSM_X4(bh[p], base + Q_B + b_lane_off + p * 1280 + koff);
#pragma unroll
            for (int mt = 0; mt < 2; mt++) {
                uint32_t ah[4];
                LDSM_X4(ah, base + Q_A + a_lane_off + mt * 1280 + koff);
#pragma unroll
                for (int nt = 0; nt < 8; nt++) {
                    const int p = nt >> 1, s2 = (nt & 1) * 2;
                    MMA16816H(acc[mt][nt], ah, bh[p][s2], bh[p][s2 + 1]);
                }
            }
        }
    }

    const int qr = lane >> 2;
    const int qc = (lane & 3) * 2;
#pragma unroll
    for (int mt = 0; mt < 2; mt++) {
#pragma unroll
        for (int nt = 0; nt < 8; nt++) {
            const int row = rBase + wm * 32 + mt * 16 + qr;
            const int col = cBase + wn * 64 + nt * 8 + qc;
            const float b0 = bias[col], b1 = bias[col + 1];
            float v00 = acc[mt][nt][0] + b0, v01 = acc[mt][nt][1] + b1;
            float v10 = acc[mt][nt][2] + b0, v11 = acc[mt][nt][3] + b1;
            if (C) {
                *(float2*)(C + (size_t)row * EMB + col) = make_float2(v00, v01);
                *(float2*)(C + (size_t)(row + 8) * EMB + col) = make_float2(v10, v11);
            } else {
                *(uint32_t*)(C16 + (size_t)row * EMB + col) = pk2h(v00, v01);
                *(uint32_t*)(C16 + (size_t)(row + 8) * EMB + col) = pk2h(v10, v11);
            }
        }
    }
}

// ---------------------------------------------------------------------------
// oproj: fp16 1-term GEMM, BM=128, BN=64 (measured-good config).
// ---------------------------------------------------------------------------
__global__ __launch_bounds__(256, 2) void oproj_f16_kernel(
    const __half* __restrict__ A, const __half* __restrict__ W,
    const float* __restrict__ bias, float* __restrict__ C)
{
    extern __shared__ __align__(16) char smem[];
    const uint32_t sbase = smem_u32(smem);

    const int tid  = threadIdx.x;
    const int lane = tid & 31;
    const int w    = tid >> 5;
    const int wm   = w & 3;
    const int wn   = w >> 2;
    const int rBase = blockIdx.y * 128;
    const int cBase = blockIdx.x * 64;

    const int j  = lane >> 3;
    const int l8 = lane & 7;
    const uint32_t a_lane_off =
        (uint32_t)((wm * 32 + (j & 1) * 8 + l8) * 80 + (j >> 1) * 16);
    const uint32_t b_lane_off =
        (uint32_t)((wn * 32 + (j >> 1) * 8 + l8) * 80 + (j & 1) * 16);

    float acc[2][4][4];
#pragma unroll
    for (int mt = 0; mt < 2; mt++)
#pragma unroll
        for (int nt = 0; nt < 4; nt++)
#pragma unroll
            for (int e = 0; e < 4; e++) acc[mt][nt][e] = 0.f;

    auto load_stage = [&](int s, int kc) {
        const uint32_t dst0 = sbase + s * P_STAGE;
        {
            const int r = tid >> 1, c0 = (tid & 1) * 2;
            const size_t g = (size_t)(rBase + r) * KDIM + kc + c0 * 8;
            const uint32_t d = dst0 + P_A + r * 80 + c0 * 16;
            CP_ASYNC16(d,      A + g);
            CP_ASYNC16(d + 16, A + g + 8);
        }
        {
            const int r = tid >> 2, c = tid & 3;
            const size_t g = (size_t)(cBase + r) * KDIM + kc + c * 8;
            CP_ASYNC16(dst0 + P_B + r * 80 + c * 16, W + g);
        }
    };

    load_stage(0, 0); CP_COMMIT();
    load_stage(1, BK); CP_COMMIT();

    for (int i = 0; i < NCHUNK; i++) {
        if (i + 1 < NCHUNK) { CP_WAIT(1); } else { CP_WAIT(0); }
        __syncthreads();
        if (i + 2 < NCHUNK) {
            load_stage((i + 2) % 3, (i + 2) * BK);
            CP_COMMIT();
        }

        const uint32_t base = sbase + (i % 3) * P_STAGE;
#pragma unroll
        for (int ks = 0; ks < 2; ks++) {
            const uint32_t koff = ks * 32;
            uint32_t bh[2][4];
#pragma unroll
            for (int p = 0; p < 2; p++)
                LDSM_X4(bh[p], base + P_B + b_lane_off + p * 1280 + koff);
#pragma unroll
            for (int mt = 0; mt < 2; mt++) {
                uint32_t ah[4];
                LDSM_X4(ah, base + P_A + a_lane_off + mt * 1280 + koff);
#pragma unroll
                for (int nt = 0; nt < 4; nt++) {
                    const int p = nt >> 1, s2 = (nt & 1) * 2;
                    MMA16816H(acc[mt][nt], ah, bh[p][s2], bh[p][s2 + 1]);
                }
            }
        }
    }

    const int qr = lane >> 2;
    const int qc = (lane & 3) * 2;
#pragma unroll
    for (int mt = 0; mt < 2; mt++) {
#pragma unroll
        for (int nt = 0; nt < 4; nt++) {
            const int row = rBase + wm * 32 + mt * 16 + qr;
            const int col = cBase + wn * 32 + nt * 8 + qc;
            const float b0 = bias[col], b1 = bias[col + 1];
            *(float2*)(C + (size_t)row * EMB + col) =
                make_float2(acc[mt][nt][0] + b0, acc[mt][nt][1] + b1);
            *(float2*)(C + (size_t)(row + 8) * EMB + col) =
                make_float2(acc[mt][nt][2] + b0, acc[mt][nt][3] + b1);
        }
    }
}

// ---------------- batched fp32 -> fp16 conversions ---------------------------
#define HS8 (S_TOK * EMB / 8)
#define W8  (EMB * EMB / 8)
#define CVT_TOTAL (HS8 + 4 * W8)

__global__ __launch_bounds__(256) void cvt_all_kernel(
    const float* __restrict__ hs, const float* __restrict__ qw,
    const float* __restrict__ kw, const float* __restrict__ vw,
    const float* __restrict__ ow,
    __half* __restrict__ hs16, __half* __restrict__ w16)
{
    int t = blockIdx.x * blockDim.x + threadIdx.x;
    if (t >= CVT_TOTAL) return;
    const float* src;
    __half* dst;
    size_t off;
    if (t < HS8) {
        src = hs; dst = hs16; off = (size_t)t * 8;
    } else {
        int r = t - HS8;
        int wsel = r / W8;
        int loc = r - wsel * W8;
        const float* ws[4] = { qw, kw, vw, ow };
        src = ws[wsel];
        dst = w16 + (size_t)wsel * EMB * EMB;
        off = (size_t)loc * 8;
    }
    const float4* s4 = (const float4*)(src + off);
    float4 a = s4[0], b = s4[1];
    float v[8] = {a.x, a.y, a.z, a.w, b.x, b.y, b.z, b.w};
    uint32_t p[4];
#pragma unroll
    for (int k = 0; k < 4; k++) p[k] = pk2h(v[2 * k], v[2 * k + 1]);
    *(uint4*)(dst + off) = make_uint4(p[0], p[1], p[2], p[3]);
}

// ---------------- prep: RoPE + scale -> fp16 (Q hi/lo, K single) -------------
__global__ __launch_bounds__(256) void prep_qk_kernel(
    const float* __restrict__ Q, const float* __restrict__ K,
    __half* __restrict__ qh, __half* __restrict__ ql,
    __half* __restrict__ k16,
    const float* __restrict__ cosp, const float* __restrict__ sinp)
{
    int idx = blockIdx.x * blockDim.x + threadIdx.x;
    if (idx >= S_TOK * NH * 9) return;
    const int c = idx % 9;
    const int t = idx / 9;
    const int h = t % NH;
    const int s = t / NH;
    const size_t gb = (size_t)s * EMB + h * HD + c * 4;
    const size_t pb = (size_t)s * HD + c * 4;
    const float scale = rsqrtf((float)HD);

    float4 cl = *(const float4*)(cosp + pb);
    float4 sl = *(const float4*)(sinp + pb);
    float4 ch = *(const float4*)(cosp + pb + 36);
    float4 sh = *(const float4*)(sinp + pb + 36);

    {   // Q (scaled), fp16 hi + lo residual
        float4 a = *(const float4*)(Q + gb);
        float4 b = *(const float4*)(Q + gb + 36);
        float rl[4] = { (a.x * cl.x - b.x * sl.x) * scale, (a.y * cl.y - b.y * sl.y) * scale,
                        (a.z * cl.z - b.z * sl.z) * scale, (a.w * cl.w - b.w * sl.w) * scale };
        float rh[4] = { (b.x * ch.x + a.x * sh.x) * scale, (b.y * ch.y + a.y * sh.y) * scale,
                        (b.z * ch.z + a.z * sh.z) * scale, (b.w * ch.w + a.w * sh.w) * scale };
        float el[4], eh[4];
#pragma unroll
        for (int e = 0; e < 4; e++) { el[e] = rl[e] - f2h(rl[e]); eh[e] = rh[e] - f2h(rh[e]); }
        *(uint2*)(qh + gb)      = make_uint2(pk2h(rl[0], rl[1]), pk2h(rl[2], rl[3]));
        *(uint2*)(qh + gb + 36) = make_uint2(pk2h(rh[0], rh[1]), pk2h(rh[2], rh[3]));
        *(uint2*)(ql + gb)      = make_uint2(pk2h(el[0], el[1]), pk2h(el[2], el[3]));
        *(uint2*)(ql + gb + 36) = make_uint2(pk2h(eh[0], eh[1]), pk2h(eh[2], eh[3]));
    }
    {   // K (unscaled), fp16 single
        float4 a = *(const float4*)(K + gb);
        float4 b = *(const float4*)(K + gb + 36);
        float rl[4] = { a.x * cl.x - b.x * sl.x, a.y * cl.y - b.y * sl.y,
                        a.z * cl.z - b.z * sl.z, a.w * cl.w - b.w * sl.w };
        float rh[4] = { b.x * ch.x + a.x * sh.x, b.y * ch.y + a.y * sh.y,
                        b.z * ch.z + a.z * sh.z, b.w * ch.w + a.w * sh.w };
        *(uint2*)(k16 + gb)      = make_uint2(pk2h(rl[0], rl[1]), pk2h(rl[2], rl[3]));
        *(uint2*)(k16 + gb + 36) = make_uint2(pk2h(rh[0], rh[1]), pk2h(rh[2], rh[3]));
    }
}

// ---------------------------------------------------------------------------
// HMMA flash attention (R12-verified): S fp16 2-term, PV fp16 1-term.
// ---------------------------------------------------------------------------
__global__ __launch_bounds__(256, 2) void attn_mma_kernel(
    const __half* __restrict__ QH, const __half* __restrict__ QL,
    const __half* __restrict__ K16g, const __half* __restrict__ V16g,
    __half* __restrict__ O16,
    const int* __restrict__ cu, int nseg)
{
    extern __shared__ __align__(16) char asmem[];
    const uint32_t sb = smem_u32(asmem);

    const int tid  = threadIdx.x;
    const int lane = tid & 31;
    const int w    = tid >> 5;
    const int h    = blockIdx.y;
    const int q0   = blockIdx.x * 128;

    int segStart = 0, segEnd = S_TOK;
    for (int i = 0; i < nseg; i++) {
        int a = cu[i], b = cu[i + 1];
        if (q0 >= a && q0 < b) { segStart = a; segEnd = b; }
    }
    const int ntiles = (segEnd - segStart + 31) / 32;

    for (int i = tid; i < 128; i += 256) {
        *(uint4*)(asmem + AQ_H + i * A_ROWB + 144) = make_uint4(0, 0, 0, 0);
        *(uint4*)(asmem + AQ_L + i * A_ROWB + 144) = make_uint4(0, 0, 0, 0);
    }
    for (int i = tid; i < 3 * 32; i += 256) {
        const int b = i / 32, r = i % 32;
        char* rowp = asmem + AKV0 + b * KVS + r * A_ROWB + 144;
        *(uint4*)(rowp + KO) = make_uint4(0, 0, 0, 0);
        *(uint4*)(rowp + VO) = make_uint4(0, 0, 0, 0);
    }

    for (int i = tid; i < 128 * 9; i += 256) {
        const int r = i / 9, c = i % 9;
        const size_t g = (size_t)(q0 + r) * EMB + h * HD + c * 8;
        CP_ASYNC16(sb + AQ_H + r * A_ROWB + c * 16, QH + g);
        CP_ASYNC16(sb + AQ_L + r * A_ROWB + c * 16, QL + g);
    }
    CP_COMMIT();

    auto stage_kv = [&](int tt) {
        const int b = tt % 3;
        const int kt = segStart + tt * 32;
        const uint32_t dst0 = sb + AKV0 + b * KVS;
        for (int i = tid; i < 32 * 9; i += 256) {
            const int r = i / 9, c = i % 9;
            const int key = kt + r;
            if (key < segEnd) {
                const size_t g = (size_t)key * EMB + h * HD + c * 8;
                const uint32_t d = dst0 + r * A_ROWB + c * 16;
                CP_ASYNC16(d + KO, K16g + g);
                CP_ASYNC16(d + VO, V16g + g);
            }
        }
    };

    stage_kv(0); CP_COMMIT();
    if (ntiles > 1) { stage_kv(1); CP_COMMIT(); }

    const int j  = lane >> 3;
    const int l8 = lane & 7;
    const uint32_t q_off  = (uint32_t)((16 * w + (j & 1) * 8 + l8) * A_ROWB + (j >> 1) * 16);
    const uint32_t bs_off = (uint32_t)(((j >> 1) * 8 + l8) * A_ROWB + (j & 1) * 16);
    const uint32_t v_off  = (uint32_t)(((j & 1) * 8 + l8) * A_ROWB + (j >> 1) * 16);

    const int qr = lane >> 2;
    const int lc = lane & 3;

    float acc_o[10][4];
#pragma unroll
    for (int dt = 0; dt < 10; dt++)
#pragma unroll
        for (int e = 0; e < 4; e++) acc_o[dt][e] = 0.f;
    float lsum0 = 0.f, lsum1 = 0.f;

    for (int tt = 0; tt < ntiles; tt++) {
        const int kt = segStart + tt * 32;
        if (tt + 1 < ntiles) { CP_WAIT(1); } else { CP_WAIT(0); }
        __syncthreads();
        if (tt + 2 < ntiles) { stage_kv(tt + 2); CP_COMMIT(); }

        const uint32_t kvb = sb + AKV0 + (tt % 3) * KVS;

        if (kt + 32 > segEnd) {
            for (int i = tid; i < 32 * 9; i += 256) {
                const int r = i / 9, c = i % 9;
                if (kt + r >= segEnd) {
                    char* dp2 = asmem + (kvb - sb) + r * A_ROWB + c * 16;
                    *(uint4*)(dp2 + KO) = make_uint4(0, 0, 0, 0);
                    *(uint4*)(dp2 + VO) = make_uint4(0, 0, 0, 0);
                }
            }
            __syncthreads();
        }

        float acc_s[4][4];
#pragma unroll
        for (int nt = 0; nt < 4; nt++)
#pragma unroll
            for (int e = 0; e < 4; e++) acc_s[nt][e] = 0.f;

#pragma unroll
        for (int kc = 0; kc < 5; kc++) {
            uint32_t qhr[4], qlr[4];
            const uint32_t ao = sb + AQ_H + q_off + kc * 32;
            LDSM_X4(qhr, ao);
            LDSM_X4(qlr, ao + (AQ_L - AQ_H));
#pragma unroll
            for (int np = 0; np < 2; np++) {
                uint32_t bh[4];
                const uint32_t bo = kvb + KO + bs_off + np * (16 * A_ROWB) + kc * 32;
                LDSM_X4(bh, bo);
                MMA16816H(acc_s[2 * np],     qhr, bh[0], bh[1]);
                MMA16816H(acc_s[2 * np],     qlr, bh[0], bh[1]);
                MMA16816H(acc_s[2 * np + 1], qhr, bh[2], bh[3]);
                MMA16816H(acc_s[2 * np + 1], qlr, bh[2], bh[3]);
            }
        }

#pragma unroll
        for (int nt = 0; nt < 4; nt++) {
            const int colb = kt + nt * 8 + lc * 2;
            float p0 = (colb     < segEnd) ? __expf(acc_s[nt][0]) : 0.f;
            float p1 = (colb + 1 < segEnd) ? __expf(acc_s[nt][1]) : 0.f;
            float p2 = (colb     < segEnd) ? __expf(acc_s[nt][2]) : 0.f;
            float p3 = (colb + 1 < segEnd) ? __expf(acc_s[nt][3]) : 0.f;
            lsum0 += p0 + p1;
            lsum1 += p2 + p3;
            acc_s[nt][0] = p0; acc_s[nt][1] = p1;
            acc_s[nt][2] = p2; acc_s[nt][3] = p3;
        }

#pragma unroll
        for (int kc = 0; kc < 2; kc++) {
            uint32_t pa[4];
            const float* s0 = acc_s[2 * kc];
            const float* s1 = acc_s[2 * kc + 1];
            pa[0] = pk2h(s0[0], s0[1]); pa[1] = pk2h(s0[2], s0[3]);
            pa[2] = pk2h(s1[0], s1[1]); pa[3] = pk2h(s1[2], s1[3]);
#pragma unroll
            for (int dp = 0; dp < 5; dp++) {
                uint32_t vh[4];
                const uint32_t vo = kvb + VO + v_off + kc * (16 * A_ROWB) + dp * 32;
                LDSM_X4_T(vh, vo);
                MMA16816H(acc_o[2 * dp],     pa, vh[0], vh[1]);
                MMA16816H(acc_o[2 * dp + 1], pa, vh[2], vh[3]);
            }
        }
    }

    lsum0 += __shfl_xor_sync(0xffffffffu, lsum0, 1);
    lsum0 += __shfl_xor_sync(0xffffffffu, lsum0, 2);
    lsum1 += __shfl_xor_sync(0xffffffffu, lsum1, 1);
    lsum1 += __shfl_xor_sync(0xffffffffu, lsum1, 2);
    const float inv0 = 1.0f / lsum0;
    const float inv1 = 1.0f / lsum1;
    const int row0 = q0 + 16 * w + qr;
    const int row1 = row0 + 8;
#pragma unroll
    for (int dt = 0; dt < 9; dt++) {
        const int d = dt * 8 + lc * 2;
        *(uint32_t*)(O16 + (size_t)row0 * EMB + h * HD + d) =
            pk2h(acc_o[dt][0] * inv0, acc_o[dt][1] * inv0);
        *(uint32_t*)(O16 + (size_t)row1 * EMB + h * HD + d) =
            pk2h(acc_o[dt][2] * inv1, acc_o[dt][3] * inv1);
    }
}

// ---------------------------------------------------------------------------
extern "C" void kernel_launch(void* const* d_in, const int* in_sizes, int n_in,
                              void* d_out, int out_size)
{
    const float* hs   = (const float*)d_in[0];
    const float* qw   = (const float*)d_in[1];
    const float* qb   = (const float*)d_in[2];
    const float* kw   = (const float*)d_in[3];
    const float* kb   = (const float*)d_in[4];
    const float* vw   = (const float*)d_in[5];
    const float* vb   = (const float*)d_in[6];
    const float* ow   = (const float*)d_in[7];
    const float* ob   = (const float*)d_in[8];
    const float* cosp = (const float*)d_in[9];
    const float* sinp = (const float*)d_in[10];
    const int*   cu   = (const int*)d_in[11];
    const int nseg = in_sizes[11] - 1;

    float *qp, *kp;
    __half *qh, *ql, *k16, *v16, *hs16, *a16, *w16;
    cudaGetSymbolAddress((void**)&qp, g_q);
    cudaGetSymbolAddress((void**)&kp, g_k);
    cudaGetSymbolAddress((void**)&qh, g_q_hi);
    cudaGetSymbolAddress((void**)&ql, g_q_lo);
    cudaGetSymbolAddress((void**)&k16, g_k_16);
    cudaGetSymbolAddress((void**)&v16, g_v_16);
    cudaGetSymbolAddress((void**)&hs16, g_hs16);
    cudaGetSymbolAddress((void**)&a16, g_a16);
    cudaGetSymbolAddress((void**)&w16, g_w16);

    cudaFuncSetAttribute(qkv_f16_kernel,
                         cudaFuncAttributeMaxDynamicSharedMemorySize, QKV_SMEM);
    cudaFuncSetAttribute(oproj_f16_kernel,
                         cudaFuncAttributeMaxDynamicSharedMemorySize, PRJ_SMEM);
    cudaFuncSetAttribute(attn_mma_kernel,
                         cudaFuncAttributeMaxDynamicSharedMemorySize, ATTN_SMEM);

    // 0) conversions: hs + 4 weights -> fp16
    cvt_all_kernel<<<(CVT_TOTAL + 255) / 256, 256>>>(
        hs, qw, kw, vw, ow, hs16, w16);

    // 1) Q/K/V projections (fp16 1-term, BN=128)
    qkv_f16_kernel<<<dim3(EMB / 128, S_TOK / 128, 3), 256, QKV_SMEM>>>(
        hs16, w16, qb, kb, vb, qp, kp, v16);

    // 2) prep: RoPE + scale -> Q fp16 hi/lo, K fp16
    prep_qk_kernel<<<(S_TOK * NH * 9 + 255) / 256, 256>>>(
        qp, kp, qh, ql, k16, cosp, sinp);

    // 3) attention (S fp16 2-term, PV fp16 1-term) -> a16
    attn_mma_kernel<<<dim3(S_TOK / 128, NH), 256, ATTN_SMEM>>>(
        qh, ql, k16, v16, a16, cu, nseg);

    // 4) O projection (fp16 1-term, BN=64) -> d_out
    oproj_f16_kernel<<<dim3(EMB / 64, S_TOK / 128), 256, PRJ_SMEM>>>(
        a16, w16 + 3 * (size_t)EMB * EMB, ob, (float*)d_out);
}

// round 14
// speedup vs baseline: 1.0702x; 1.0702x over previous
#include <cuda_runtime.h>
#include <cuda_bf16.h>
#include <cuda_fp16.h>
#include <cstdint>
#include <math.h>

#define S_TOK 2048
#define EMB   1152
#define NH    16
#define HD    72
#define KDIM  1152
#define BK    32
#define NCHUNK (KDIM / BK)          // 36

// ---- fp16 1-term GEMM, BN=64 (qkv / oproj): 3-stage ----
#define P_A 0
#define P_B 10240
#define P_STAGE 15360
#define PRJ_SMEM (3 * P_STAGE)      // 46080

// ---- attention smem: Q fp16 single + 3 KV stages (K fp16, V fp16) ----
#define A_ROWB 176
#define AQ   0
#define AKV0 22528
#define KO   0
#define VO   5632
#define KVS  11264
#define ATTN_SMEM (22528 + 3 * KVS)   // 56320

// ---------------- scratch ----------------------------------------------------
__device__ __align__(16) __half g_qpre[S_TOK * EMB];   // qkv Q out (pre-RoPE)
__device__ __align__(16) __half g_kpre[S_TOK * EMB];   // qkv K out (pre-RoPE)
__device__ __align__(16) __half g_q16 [S_TOK * EMB];   // prep Q out (RoPE+scale)
__device__ __align__(16) __half g_k16 [S_TOK * EMB];   // prep K out (RoPE)
__device__ __align__(16) __half g_v16 [S_TOK * EMB];   // qkv V out
__device__ __align__(16) __half g_hs16[S_TOK * EMB];
__device__ __align__(16) __half g_a16 [S_TOK * EMB];
__device__ __align__(16) __half g_w16 [4][EMB * EMB];

// ---------------- helpers ----------------------------------------------------
__device__ __forceinline__ uint32_t smem_u32(const void* p) {
    uint32_t a;
    asm("{ .reg .u64 t; cvta.to.shared.u64 t, %1; cvt.u32.u64 %0, t; }"
        : "=r"(a) : "l"(p));
    return a;
}

#define CP_ASYNC16(dst, src) \
    asm volatile("cp.async.cg.shared.global [%0], [%1], 16;" :: "r"(dst), "l"(src))
#define CP_COMMIT() asm volatile("cp.async.commit_group;" ::: "memory")
#define CP_WAIT(n)  asm volatile("cp.async.wait_group %0;" :: "n"(n) : "memory")

#define LDSM_X4(r, addr) \
    asm volatile("ldmatrix.sync.aligned.m8n8.x4.shared.b16 {%0,%1,%2,%3}, [%4];" \
        : "=r"((r)[0]), "=r"((r)[1]), "=r"((r)[2]), "=r"((r)[3]) : "r"(addr))
#define LDSM_X4_T(r, addr) \
    asm volatile("ldmatrix.sync.aligned.m8n8.x4.trans.shared.b16 {%0,%1,%2,%3}, [%4];" \
        : "=r"((r)[0]), "=r"((r)[1]), "=r"((r)[2]), "=r"((r)[3]) : "r"(addr))

#define MMA16816H(d, a, b0, b1) \
    asm volatile("mma.sync.aligned.m16n8k16.row.col.f32.f16.f16.f32 " \
        "{%0,%1,%2,%3}, {%4,%5,%6,%7}, {%8,%9}, {%0,%1,%2,%3};" \
        : "+f"((d)[0]), "+f"((d)[1]), "+f"((d)[2]), "+f"((d)[3]) \
        : "r"((a)[0]), "r"((a)[1]), "r"((a)[2]), "r"((a)[3]), "r"(b0), "r"(b1))

__device__ __forceinline__ uint32_t pk2h(float lo, float hi) {
    uint32_t r;
    asm("cvt.rn.f16x2.f32 %0, %1, %2;" : "=r"(r) : "f"(hi), "f"(lo));
    return r;
}

// ---------------------------------------------------------------------------
// fp16 1-term GEMM: BM=128, BN=64, BK=32, 3-stage. Outputs fp16 or fp32.
// ---------------------------------------------------------------------------
__device__ __forceinline__ void gemm_f16_tile(
    const __half* __restrict__ A, const __half* __restrict__ W,
    const float* __restrict__ bias, float* __restrict__ C,
    __half* __restrict__ C16)
{
    extern __shared__ __align__(16) char smem[];
    const uint32_t sbase = smem_u32(smem);

    const int tid  = threadIdx.x;
    const int lane = tid & 31;
    const int w    = tid >> 5;
    const int wm   = w & 3;
    const int wn   = w >> 2;
    const int rBase = blockIdx.y * 128;
    const int cBase = blockIdx.x * 64;

    const int j  = lane >> 3;
    const int l8 = lane & 7;
    const uint32_t a_lane_off =
        (uint32_t)((wm * 32 + (j & 1) * 8 + l8) * 80 + (j >> 1) * 16);
    const uint32_t b_lane_off =
        (uint32_t)((wn * 32 + (j >> 1) * 8 + l8) * 80 + (j & 1) * 16);

    float acc[2][4][4];
#pragma unroll
    for (int mt = 0; mt < 2; mt++)
#pragma unroll
        for (int nt = 0; nt < 4; nt++)
#pragma unroll
            for (int e = 0; e < 4; e++) acc[mt][nt][e] = 0.f;

    auto load_stage = [&](int s, int kc) {
        const uint32_t dst0 = sbase + s * P_STAGE;
        {
            const int r = tid >> 1, c0 = (tid & 1) * 2;
            const size_t g = (size_t)(rBase + r) * KDIM + kc + c0 * 8;
            const uint32_t d = dst0 + P_A + r * 80 + c0 * 16;
            CP_ASYNC16(d,      A + g);
            CP_ASYNC16(d + 16, A + g + 8);
        }
        {
            const int r = tid >> 2, c = tid & 3;
            const size_t g = (size_t)(cBase + r) * KDIM + kc + c * 8;
            CP_ASYNC16(dst0 + P_B + r * 80 + c * 16, W + g);
        }
    };

    load_stage(0, 0); CP_COMMIT();
    load_stage(1, BK); CP_COMMIT();

    for (int i = 0; i < NCHUNK; i++) {
        if (i + 1 < NCHUNK) { CP_WAIT(1); } else { CP_WAIT(0); }
        __syncthreads();
        if (i + 2 < NCHUNK) {
            load_stage((i + 2) % 3, (i + 2) * BK);
            CP_COMMIT();
        }

        const uint32_t base = sbase + (i % 3) * P_STAGE;
#pragma unroll
        for (int ks = 0; ks < 2; ks++) {
            const uint32_t koff = ks * 32;
            uint32_t bh[2][4];
#pragma unroll
            for (int p = 0; p < 2; p++)
                LDSM_X4(bh[p], base + P_B + b_lane_off + p * 1280 + koff);
#pragma unroll
            for (int mt = 0; mt < 2; mt++) {
                uint32_t ah[4];
                LDSM_X4(ah, base + P_A + a_lane_off + mt * 1280 + koff);
#pragma unroll
                for (int nt = 0; nt < 4; nt++) {
                    const int p = nt >> 1, s2 = (nt & 1) * 2;
                    MMA16816H(acc[mt][nt], ah, bh[p][s2], bh[p][s2 + 1]);
                }
            }
        }
    }

    const int qr = lane >> 2;
    const int qc = (lane & 3) * 2;
#pragma unroll
    for (int mt = 0; mt < 2; mt++) {
#pragma unroll
        for (int nt = 0; nt < 4; nt++) {
            const int row = rBase + wm * 32 + mt * 16 + qr;
            const int col = cBase + wn * 32 + nt * 8 + qc;
            const float b0 = bias[col], b1 = bias[col + 1];
            float v00 = acc[mt][nt][0] + b0, v01 = acc[mt][nt][1] + b1;
            float v10 = acc[mt][nt][2] + b0, v11 = acc[mt][nt][3] + b1;
            if (C) {
                *(float2*)(C + (size_t)row * EMB + col) = make_float2(v00, v01);
                *(float2*)(C + (size_t)(row + 8) * EMB + col) = make_float2(v10, v11);
            } else {
                *(uint32_t*)(C16 + (size_t)row * EMB + col) = pk2h(v00, v01);
                *(uint32_t*)(C16 + (size_t)(row + 8) * EMB + col) = pk2h(v10, v11);
            }
        }
    }
}

// Q/K/V projections, all outputs fp16. z selects matrix.
__global__ __launch_bounds__(256, 2) void qkv_f16_kernel(
    const __half* __restrict__ hs16, const __half* __restrict__ w16,
    const float* __restrict__ qb, const float* __restrict__ kb,
    const float* __restrict__ vb,
    __half* __restrict__ Qpre, __half* __restrict__ Kpre,
    __half* __restrict__ V16)
{
    const __half* W = w16 + (size_t)blockIdx.z * EMB * EMB;
    if (blockIdx.z == 0)
        gemm_f16_tile(hs16, W, qb, nullptr, Qpre);
    else if (blockIdx.z == 1)
        gemm_f16_tile(hs16, W, kb, nullptr, Kpre);
    else
        gemm_f16_tile(hs16, W, vb, nullptr, V16);
}

__global__ __launch_bounds__(256, 2) void oproj_f16_kernel(
    const __half* __restrict__ A, const __half* __restrict__ W,
    const float* __restrict__ bias, float* __restrict__ C)
{
    gemm_f16_tile(A, W, bias, C, nullptr);
}

// ---------------- batched fp32 -> fp16 conversions ---------------------------
#define HS8 (S_TOK * EMB / 8)
#define W8  (EMB * EMB / 8)
#define CVT_TOTAL (HS8 + 4 * W8)

__global__ __launch_bounds__(256) void cvt_all_kernel(
    const float* __restrict__ hs, const float* __restrict__ qw,
    const float* __restrict__ kw, const float* __restrict__ vw,
    const float* __restrict__ ow,
    __half* __restrict__ hs16, __half* __restrict__ w16)
{
    int t = blockIdx.x * blockDim.x + threadIdx.x;
    if (t >= CVT_TOTAL) return;
    const float* src;
    __half* dst;
    size_t off;
    if (t < HS8) {
        src = hs; dst = hs16; off = (size_t)t * 8;
    } else {
        int r = t - HS8;
        int wsel = r / W8;
        int loc = r - wsel * W8;
        const float* ws[4] = { qw, kw, vw, ow };
        src = ws[wsel];
        dst = w16 + (size_t)wsel * EMB * EMB;
        off = (size_t)loc * 8;
    }
    const float4* s4 = (const float4*)(src + off);
    float4 a = s4[0], b = s4[1];
    float v[8] = {a.x, a.y, a.z, a.w, b.x, b.y, b.z, b.w};
    uint32_t p[4];
#pragma unroll
    for (int k = 0; k < 4; k++) p[k] = pk2h(v[2 * k], v[2 * k + 1]);
    *(uint4*)(dst + off) = make_uint4(p[0], p[1], p[2], p[3]);
}

// ---------------- prep: RoPE (+scale for Q) on fp16 inputs -> fp16 ----------
__global__ __launch_bounds__(256) void prep_qk_kernel(
    const __half* __restrict__ Qpre, const __half* __restrict__ Kpre,
    __half* __restrict__ Qr, __half* __restrict__ Kr,
    const float* __restrict__ cosp, const float* __restrict__ sinp)
{
    int idx = blockIdx.x * blockDim.x + threadIdx.x;
    if (idx >= S_TOK * NH * 9) return;
    const int c = idx % 9;
    const int t = idx / 9;
    const int h = t % NH;
    const int s = t / NH;
    const size_t gb = (size_t)s * EMB + h * HD + c * 4;
    const size_t pb = (size_t)s * HD + c * 4;
    const float scale = rsqrtf((float)HD);

    float4 cl = *(const float4*)(cosp + pb);
    float4 sl = *(const float4*)(sinp + pb);
    float4 ch = *(const float4*)(cosp + pb + 36);
    float4 sh = *(const float4*)(sinp + pb + 36);

    {   // Q (scaled)
        float a0 = __half2float(Qpre[gb + 0]), a1 = __half2float(Qpre[gb + 1]);
        float a2 = __half2float(Qpre[gb + 2]), a3 = __half2float(Qpre[gb + 3]);
        float b0 = __half2float(Qpre[gb + 36]), b1 = __half2float(Qpre[gb + 37]);
        float b2 = __half2float(Qpre[gb + 38]), b3 = __half2float(Qpre[gb + 39]);
        float rl[4] = { (a0 * cl.x - b0 * sl.x) * scale, (a1 * cl.y - b1 * sl.y) * scale,
                        (a2 * cl.z - b2 * sl.z) * scale, (a3 * cl.w - b3 * sl.w) * scale };
        float rh[4] = { (b0 * ch.x + a0 * sh.x) * scale, (b1 * ch.y + a1 * sh.y) * scale,
                        (b2 * ch.z + a2 * sh.z) * scale, (b3 * ch.w + a3 * sh.w) * scale };
        *(uint2*)(Qr + gb)      = make_uint2(pk2h(rl[0], rl[1]), pk2h(rl[2], rl[3]));
        *(uint2*)(Qr + gb + 36) = make_uint2(pk2h(rh[0], rh[1]), pk2h(rh[2], rh[3]));
    }
    {   // K (unscaled)
        float a0 = __half2float(Kpre[gb + 0]), a1 = __half2float(Kpre[gb + 1]);
        float a2 = __half2float(Kpre[gb + 2]), a3 = __half2float(Kpre[gb + 3]);
        float b0 = __half2float(Kpre[gb + 36]), b1 = __half2float(Kpre[gb + 37]);
        float b2 = __half2float(Kpre[gb + 38]), b3 = __half2float(Kpre[gb + 39]);
        float rl[4] = { a0 * cl.x - b0 * sl.x, a1 * cl.y - b1 * sl.y,
                        a2 * cl.z - b2 * sl.z, a3 * cl.w - b3 * sl.w };
        float rh[4] = { b0 * ch.x + a0 * sh.x, b1 * ch.y + a1 * sh.y,
                        b2 * ch.z + a2 * sh.z, b3 * ch.w + a3 * sh.w };
        *(uint2*)(Kr + gb)      = make_uint2(pk2h(rl[0], rl[1]), pk2h(rl[2], rl[3]));
        *(uint2*)(Kr + gb + 36) = make_uint2(pk2h(rh[0], rh[1]), pk2h(rh[2], rh[3]));
    }
}

// ---------------------------------------------------------------------------
// HMMA flash attention: S fp16 1-term, PV fp16 1-term.
// ---------------------------------------------------------------------------
__global__ __launch_bounds__(256, 2) void attn_mma_kernel(
    const __half* __restrict__ Q16g,
    const __half* __restrict__ K16g, const __half* __restrict__ V16g,
    __half* __restrict__ O16,
    const int* __restrict__ cu, int nseg)
{
    extern __shared__ __align__(16) char asmem[];
    const uint32_t sb = smem_u32(asmem);

    const int tid  = threadIdx.x;
    const int lane = tid & 31;
    const int w    = tid >> 5;
    const int h    = blockIdx.y;
    const int q0   = blockIdx.x * 128;

    int segStart = 0, segEnd = S_TOK;
    for (int i = 0; i < nseg; i++) {
        int a = cu[i], b = cu[i + 1];
        if (q0 >= a && q0 < b) { segStart = a; segEnd = b; }
    }
    const int ntiles = (segEnd - segStart + 31) / 32;

    // zero pad bytes (dims 72..79): Q rows + all 3 KV stage buffers (K, V)
    for (int i = tid; i < 128; i += 256) {
        *(uint4*)(asmem + AQ + i * A_ROWB + 144) = make_uint4(0, 0, 0, 0);
    }
    for (int i = tid; i < 3 * 32; i += 256) {
        const int b = i / 32, r = i % 32;
        char* rowp = asmem + AKV0 + b * KVS + r * A_ROWB + 144;
        *(uint4*)(rowp + KO) = make_uint4(0, 0, 0, 0);
        *(uint4*)(rowp + VO) = make_uint4(0, 0, 0, 0);
    }

    for (int i = tid; i < 128 * 9; i += 256) {
        const int r = i / 9, c = i % 9;
        const size_t g = (size_t)(q0 + r) * EMB + h * HD + c * 8;
        CP_ASYNC16(sb + AQ + r * A_ROWB + c * 16, Q16g + g);
    }
    CP_COMMIT();

    auto stage_kv = [&](int tt) {
        const int b = tt % 3;
        const int kt = segStart + tt * 32;
        const uint32_t dst0 = sb + AKV0 + b * KVS;
        for (int i = tid; i < 32 * 9; i += 256) {
            const int r = i / 9, c = i % 9;
            const int key = kt + r;
            if (key < segEnd) {
                const size_t g = (size_t)key * EMB + h * HD + c * 8;
                const uint32_t d = dst0 + r * A_ROWB + c * 16;
                CP_ASYNC16(d + KO, K16g + g);
                CP_ASYNC16(d + VO, V16g + g);
            }
        }
    };

    stage_kv(0); CP_COMMIT();
    if (ntiles > 1) { stage_kv(1); CP_COMMIT(); }

    const int j  = lane >> 3;
    const int l8 = lane & 7;
    const uint32_t q_off  = (uint32_t)((16 * w + (j & 1) * 8 + l8) * A_ROWB + (j >> 1) * 16);
    const uint32_t bs_off = (uint32_t)(((j >> 1) * 8 + l8) * A_ROWB + (j & 1) * 16);
    const uint32_t v_off  = (uint32_t)(((j & 1) * 8 + l8) * A_ROWB + (j >> 1) * 16);

    const int qr = lane >> 2;
    const int lc = lane & 3;

    float acc_o[10][4];
#pragma unroll
    for (int dt = 0; dt < 10; dt++)
#pragma unroll
        for (int e = 0; e < 4; e++) acc_o[dt][e] = 0.f;
    float lsum0 = 0.f, lsum1 = 0.f;

    for (int tt = 0; tt < ntiles; tt++) {
        const int kt = segStart + tt * 32;
        if (tt + 1 < ntiles) { CP_WAIT(1); } else { CP_WAIT(0); }
        __syncthreads();
        if (tt + 2 < ntiles) { stage_kv(tt + 2); CP_COMMIT(); }

        const uint32_t kvb = sb + AKV0 + (tt % 3) * KVS;

        if (kt + 32 > segEnd) {
            for (int i = tid; i < 32 * 9; i += 256) {
                const int r = i / 9, c = i % 9;
                if (kt + r >= segEnd) {
                    char* dp2 = asmem + (kvb - sb) + r * A_ROWB + c * 16;
                    *(uint4*)(dp2 + KO) = make_uint4(0, 0, 0, 0);
                    *(uint4*)(dp2 + VO) = make_uint4(0, 0, 0, 0);
                }
            }
            __syncthreads();
        }

        // ---- S = Q K^T (fp16 1-term), 32 keys -----------------------------
        float acc_s[4][4];
#pragma unroll
        for (int nt = 0; nt < 4; nt++)
#pragma unroll
            for (int e = 0; e < 4; e++) acc_s[nt][e] = 0.f;

#pragma unroll
        for (int kc = 0; kc < 5; kc++) {
            uint32_t qhr[4];
            LDSM_X4(qhr, sb + AQ + q_off + kc * 32);
#pragma unroll
            for (int np = 0; np < 2; np++) {
                uint32_t bh[4];
                const uint32_t bo = kvb + KO + bs_off + np * (16 * A_ROWB) + kc * 32;
                LDSM_X4(bh, bo);
                MMA16816H(acc_s[2 * np],     qhr, bh[0], bh[1]);
                MMA16816H(acc_s[2 * np + 1], qhr, bh[2], bh[3]);
            }
        }

        // ---- softmax (unnormalized) + mask --------------------------------
#pragma unroll
        for (int nt = 0; nt < 4; nt++) {
            const int colb = kt + nt * 8 + lc * 2;
            float p0 = (colb     < segEnd) ? __expf(acc_s[nt][0]) : 0.f;
            float p1 = (colb + 1 < segEnd) ? __expf(acc_s[nt][1]) : 0.f;
            float p2 = (colb     < segEnd) ? __expf(acc_s[nt][2]) : 0.f;
            float p3 = (colb + 1 < segEnd) ? __expf(acc_s[nt][3]) : 0.f;
            lsum0 += p0 + p1;
            lsum1 += p2 + p3;
            acc_s[nt][0] = p0; acc_s[nt][1] = p1;
            acc_s[nt][2] = p2; acc_s[nt][3] = p3;
        }

        // ---- O += P V (fp16 1-term) ---------------------------------------
#pragma unroll
        for (int kc = 0; kc < 2; kc++) {
            uint32_t pa[4];
            const float* s0 = acc_s[2 * kc];
            const float* s1 = acc_s[2 * kc + 1];
            pa[0] = pk2h(s0[0], s0[1]); pa[1] = pk2h(s0[2], s0[3]);
            pa[2] = pk2h(s1[0], s1[1]); pa[3] = pk2h(s1[2], s1[3]);
#pragma unroll
            for (int dp = 0; dp < 5; dp++) {
                uint32_t vh[4];
                const uint32_t vo = kvb + VO + v_off + kc * (16 * A_ROWB) + dp * 32;
                LDSM_X4_T(vh, vo);
                MMA16816H(acc_o[2 * dp],     pa, vh[0], vh[1]);
                MMA16816H(acc_o[2 * dp + 1], pa, vh[2], vh[3]);
            }
        }
    }

    // ---- epilogue: normalize, write fp16 ----------------------------------
    lsum0 += __shfl_xor_sync(0xffffffffu, lsum0, 1);
    lsum0 += __shfl_xor_sync(0xffffffffu, lsum0, 2);
    lsum1 += __shfl_xor_sync(0xffffffffu, lsum1, 1);
    lsum1 += __shfl_xor_sync(0xffffffffu, lsum1, 2);
    const float inv0 = 1.0f / lsum0;
    const float inv1 = 1.0f / lsum1;
    const int row0 = q0 + 16 * w + qr;
    const int row1 = row0 + 8;
#pragma unroll
    for (int dt = 0; dt < 9; dt++) {
        const int d = dt * 8 + lc * 2;
        *(uint32_t*)(O16 + (size_t)row0 * EMB + h * HD + d) =
            pk2h(acc_o[dt][0] * inv0, acc_o[dt][1] * inv0);
        *(uint32_t*)(O16 + (size_t)row1 * EMB + h * HD + d) =
            pk2h(acc_o[dt][2] * inv1, acc_o[dt][3] * inv1);
    }
}

// ---------------------------------------------------------------------------
extern "C" void kernel_launch(void* const* d_in, const int* in_sizes, int n_in,
                              void* d_out, int out_size)
{
    const float* hs   = (const float*)d_in[0];
    const float* qw   = (const float*)d_in[1];
    const float* qb   = (const float*)d_in[2];
    const float* kw   = (const float*)d_in[3];
    const float* kb   = (const float*)d_in[4];
    const float* vw   = (const float*)d_in[5];
    const float* vb   = (const float*)d_in[6];
    const float* ow   = (const float*)d_in[7];
    const float* ob   = (const float*)d_in[8];
    const float* cosp = (const float*)d_in[9];
    const float* sinp = (const float*)d_in[10];
    const int*   cu   = (const int*)d_in[11];
    const int nseg = in_sizes[11] - 1;

    __half *qpre, *kpre, *q16, *k16, *v16, *hs16, *a16, *w16;
    cudaGetSymbolAddress((void**)&qpre, g_qpre);
    cudaGetSymbolAddress((void**)&kpre, g_kpre);
    cudaGetSymbolAddress((void**)&q16, g_q16);
    cudaGetSymbolAddress((void**)&k16, g_k16);
    cudaGetSymbolAddress((void**)&v16, g_v16);
    cudaGetSymbolAddress((void**)&hs16, g_hs16);
    cudaGetSymbolAddress((void**)&a16, g_a16);
    cudaGetSymbolAddress((void**)&w16, g_w16);

    cudaFuncSetAttribute(qkv_f16_kernel,
                         cudaFuncAttributeMaxDynamicSharedMemorySize, PRJ_SMEM);
    cudaFuncSetAttribute(oproj_f16_kernel,
                         cudaFuncAttributeMaxDynamicSharedMemorySize, PRJ_SMEM);
    cudaFuncSetAttribute(attn_mma_kernel,
                         cudaFuncAttributeMaxDynamicSharedMemorySize, ATTN_SMEM);

    // 0) conversions: hs + 4 weights -> fp16
    cvt_all_kernel<<<(CVT_TOTAL + 255) / 256, 256>>>(
        hs, qw, kw, vw, ow, hs16, w16);

    // 1) Q/K/V projections (fp16 1-term, BN=64, all-fp16 out)
    qkv_f16_kernel<<<dim3(EMB / 64, S_TOK / 128, 3), 256, PRJ_SMEM>>>(
        hs16, w16, qb, kb, vb, qpre, kpre, v16);

    // 2) prep: RoPE + scale (fp16 in/out)
    prep_qk_kernel<<<(S_TOK * NH * 9 + 255) / 256, 256>>>(
        qpre, kpre, q16, k16, cosp, sinp);

    // 3) attention (S fp16 1-term, PV fp16 1-term) -> a16
    attn_mma_kernel<<<dim3(S_TOK / 128, NH), 256, ATTN_SMEM>>>(
        q16, k16, v16, a16, cu, nseg);

    // 4) O projection (fp16 1-term, BN=64) -> d_out
    oproj_f16_kernel<<<dim3(EMB / 64, S_TOK / 128), 256, PRJ_SMEM>>>(
        a16, w16 + 3 * (size_t)EMB * EMB, ob, (float*)d_out);
}

// round 15
// speedup vs baseline: 1.0704x; 1.0002x over previous
#include <cuda_runtime.h>
#include <cuda_bf16.h>
#include <cuda_fp16.h>
#include <cstdint>
#include <math.h>

#define S_TOK 2048
#define EMB   1152
#define NH    16
#define HD    72
#define KDIM  1152
#define BK    32
#define NCHUNK (KDIM / BK)          // 36

// ---- fp16 1-term GEMM, BN=64 (qkv / oproj): 3-stage ----
#define P_A 0
#define P_B 10240
#define P_STAGE 15360
#define PRJ_SMEM (3 * P_STAGE)      // 46080

// ---- attention smem: Q fp16 + 2 KV stages of 64 keys (K fp16, V fp16) ----
#define A_ROWB 176
#define AQ   0
#define AKV0 22528
#define KO   0
#define VO   11264
#define KVS  22528                  // 64 rows * 176 * 2 operands
#define ATTN_SMEM (22528 + 2 * KVS) // 67584

// ---------------- scratch ----------------------------------------------------
__device__ __align__(16) __half g_qpre[S_TOK * EMB];
__device__ __align__(16) __half g_kpre[S_TOK * EMB];
__device__ __align__(16) __half g_q16 [S_TOK * EMB];
__device__ __align__(16) __half g_k16 [S_TOK * EMB];
__device__ __align__(16) __half g_v16 [S_TOK * EMB];
__device__ __align__(16) __half g_hs16[S_TOK * EMB];
__device__ __align__(16) __half g_a16 [S_TOK * EMB];
__device__ __align__(16) __half g_w16 [4][EMB * EMB];

// ---------------- helpers ----------------------------------------------------
__device__ __forceinline__ uint32_t smem_u32(const void* p) {
    uint32_t a;
    asm("{ .reg .u64 t; cvta.to.shared.u64 t, %1; cvt.u32.u64 %0, t; }"
        : "=r"(a) : "l"(p));
    return a;
}

#define CP_ASYNC16(dst, src) \
    asm volatile("cp.async.cg.shared.global [%0], [%1], 16;" :: "r"(dst), "l"(src))
#define CP_COMMIT() asm volatile("cp.async.commit_group;" ::: "memory")
#define CP_WAIT(n)  asm volatile("cp.async.wait_group %0;" :: "n"(n) : "memory")

#define LDSM_X4(r, addr) \
    asm volatile("ldmatrix.sync.aligned.m8n8.x4.shared.b16 {%0,%1,%2,%3}, [%4];" \
        : "=r"((r)[0]), "=r"((r)[1]), "=r"((r)[2]), "=r"((r)[3]) : "r"(addr))
#define LDSM_X4_T(r, addr) \
    asm volatile("ldmatrix.sync.aligned.m8n8.x4.trans.shared.b16 {%0,%1,%2,%3}, [%4];" \
        : "=r"((r)[0]), "=r"((r)[1]), "=r"((r)[2]), "=r"((r)[3]) : "r"(addr))

#define MMA16816H(d, a, b0, b1) \
    asm volatile("mma.sync.aligned.m16n8k16.row.col.f32.f16.f16.f32 " \
        "{%0,%1,%2,%3}, {%4,%5,%6,%7}, {%8,%9}, {%0,%1,%2,%3};" \
        : "+f"((d)[0]), "+f"((d)[1]), "+f"((d)[2]), "+f"((d)[3]) \
        : "r"((a)[0]), "r"((a)[1]), "r"((a)[2]), "r"((a)[3]), "r"(b0), "r"(b1))

__device__ __forceinline__ uint32_t pk2h(float lo, float hi) {
    uint32_t r;
    asm("cvt.rn.f16x2.f32 %0, %1, %2;" : "=r"(r) : "f"(hi), "f"(lo));
    return r;
}

// ---------------------------------------------------------------------------
// fp16 1-term GEMM: BM=128, BN=64, BK=32, 3-stage (R12/R14-verified).
// ---------------------------------------------------------------------------
__device__ __forceinline__ void gemm_f16_tile(
    const __half* __restrict__ A, const __half* __restrict__ W,
    const float* __restrict__ bias, float* __restrict__ C,
    __half* __restrict__ C16)
{
    extern __shared__ __align__(16) char smem[];
    const uint32_t sbase = smem_u32(smem);

    const int tid  = threadIdx.x;
    const int lane = tid & 31;
    const int w    = tid >> 5;
    const int wm   = w & 3;
    const int wn   = w >> 2;
    const int rBase = blockIdx.y * 128;
    const int cBase = blockIdx.x * 64;

    const int j  = lane >> 3;
    const int l8 = lane & 7;
    const uint32_t a_lane_off =
        (uint32_t)((wm * 32 + (j & 1) * 8 + l8) * 80 + (j >> 1) * 16);
    const uint32_t b_lane_off =
        (uint32_t)((wn * 32 + (j >> 1) * 8 + l8) * 80 + (j & 1) * 16);

    float acc[2][4][4];
#pragma unroll
    for (int mt = 0; mt < 2; mt++)
#pragma unroll
        for (int nt = 0; nt < 4; nt++)
#pragma unroll
            for (int e = 0; e < 4; e++) acc[mt][nt][e] = 0.f;

    auto load_stage = [&](int s, int kc) {
        const uint32_t dst0 = sbase + s * P_STAGE;
        {
            const int r = tid >> 1, c0 = (tid & 1) * 2;
            const size_t g = (size_t)(rBase + r) * KDIM + kc + c0 * 8;
            const uint32_t d = dst0 + P_A + r * 80 + c0 * 16;
            CP_ASYNC16(d,      A + g);
            CP_ASYNC16(d + 16, A + g + 8);
        }
        {
            const int r = tid >> 2, c = tid & 3;
            const size_t g = (size_t)(cBase + r) * KDIM + kc + c * 8;
            CP_ASYNC16(dst0 + P_B + r * 80 + c * 16, W + g);
        }
    };

    load_stage(0, 0); CP_COMMIT();
    load_stage(1, BK); CP_COMMIT();

    for (int i = 0; i < NCHUNK; i++) {
        if (i + 1 < NCHUNK) { CP_WAIT(1); } else { CP_WAIT(0); }
        __syncthreads();
        if (i + 2 < NCHUNK) {
            load_stage((i + 2) % 3, (i + 2) * BK);
            CP_COMMIT();
        }

        const uint32_t base = sbase + (i % 3) * P_STAGE;
#pragma unroll
        for (int ks = 0; ks < 2; ks++) {
            const uint32_t koff = ks * 32;
            uint32_t bh[2][4];
#pragma unroll
            for (int p = 0; p < 2; p++)
                LDSM_X4(bh[p], base + P_B + b_lane_off + p * 1280 + koff);
#pragma unroll
            for (int mt = 0; mt < 2; mt++) {
                uint32_t ah[4];
                LDSM_X4(ah, base + P_A + a_lane_off + mt * 1280 + koff);
#pragma unroll
                for (int nt = 0; nt < 4; nt++) {
                    const int p = nt >> 1, s2 = (nt & 1) * 2;
                    MMA16816H(acc[mt][nt], ah, bh[p][s2], bh[p][s2 + 1]);
                }
            }
        }
    }

    const int qr = lane >> 2;
    const int qc = (lane & 3) * 2;
#pragma unroll
    for (int mt = 0; mt < 2; mt++) {
#pragma unroll
        for (int nt = 0; nt < 4; nt++) {
            const int row = rBase + wm * 32 + mt * 16 + qr;
            const int col = cBase + wn * 32 + nt * 8 + qc;
            const float b0 = bias[col], b1 = bias[col + 1];
            float v00 = acc[mt][nt][0] + b0, v01 = acc[mt][nt][1] + b1;
            float v10 = acc[mt][nt][2] + b0, v11 = acc[mt][nt][3] + b1;
            if (C) {
                *(float2*)(C + (size_t)row * EMB + col) = make_float2(v00, v01);
                *(float2*)(C + (size_t)(row + 8) * EMB + col) = make_float2(v10, v11);
            } else {
                *(uint32_t*)(C16 + (size_t)row * EMB + col) = pk2h(v00, v01);
                *(uint32_t*)(C16 + (size_t)(row + 8) * EMB + col) = pk2h(v10, v11);
            }
        }
    }
}

__global__ __launch_bounds__(256, 2) void qkv_f16_kernel(
    const __half* __restrict__ hs16, const __half* __restrict__ w16,
    const float* __restrict__ qb, const float* __restrict__ kb,
    const float* __restrict__ vb,
    __half* __restrict__ Qpre, __half* __restrict__ Kpre,
    __half* __restrict__ V16)
{
    const __half* W = w16 + (size_t)blockIdx.z * EMB * EMB;
    if (blockIdx.z == 0)
        gemm_f16_tile(hs16, W, qb, nullptr, Qpre);
    else if (blockIdx.z == 1)
        gemm_f16_tile(hs16, W, kb, nullptr, Kpre);
    else
        gemm_f16_tile(hs16, W, vb, nullptr, V16);
}

__global__ __launch_bounds__(256, 2) void oproj_f16_kernel(
    const __half* __restrict__ A, const __half* __restrict__ W,
    const float* __restrict__ bias, float* __restrict__ C)
{
    gemm_f16_tile(A, W, bias, C, nullptr);
}

// ---------------- batched fp32 -> fp16 conversions ---------------------------
#define HS8 (S_TOK * EMB / 8)
#define W8  (EMB * EMB / 8)
#define CVT_TOTAL (HS8 + 4 * W8)

__global__ __launch_bounds__(256) void cvt_all_kernel(
    const float* __restrict__ hs, const float* __restrict__ qw,
    const float* __restrict__ kw, const float* __restrict__ vw,
    const float* __restrict__ ow,
    __half* __restrict__ hs16, __half* __restrict__ w16)
{
    int t = blockIdx.x * blockDim.x + threadIdx.x;
    if (t >= CVT_TOTAL) return;
    const float* src;
    __half* dst;
    size_t off;
    if (t < HS8) {
        src = hs; dst = hs16; off = (size_t)t * 8;
    } else {
        int r = t - HS8;
        int wsel = r / W8;
        int loc = r - wsel * W8;
        const float* ws[4] = { qw, kw, vw, ow };
        src = ws[wsel];
        dst = w16 + (size_t)wsel * EMB * EMB;
        off = (size_t)loc * 8;
    }
    const float4* s4 = (const float4*)(src + off);
    float4 a = s4[0], b = s4[1];
    float v[8] = {a.x, a.y, a.z, a.w, b.x, b.y, b.z, b.w};
    uint32_t p[4];
#pragma unroll
    for (int k = 0; k < 4; k++) p[k] = pk2h(v[2 * k], v[2 * k + 1]);
    *(uint4*)(dst + off) = make_uint4(p[0], p[1], p[2], p[3]);
}

// ---------------- prep: RoPE (+scale for Q) fp16 in/out (R14-verified) -------
__global__ __launch_bounds__(256) void prep_qk_kernel(
    const __half* __restrict__ Qpre, const __half* __restrict__ Kpre,
    __half* __restrict__ Qr, __half* __restrict__ Kr,
    const float* __restrict__ cosp, const float* __restrict__ sinp)
{
    int idx = blockIdx.x * blockDim.x + threadIdx.x;
    if (idx >= S_TOK * NH * 9) return;
    const int c = idx % 9;
    const int t = idx / 9;
    const int h = t % NH;
    const int s = t / NH;
    const size_t gb = (size_t)s * EMB + h * HD + c * 4;
    const size_t pb = (size_t)s * HD + c * 4;
    const float scale = rsqrtf((float)HD);

    float4 cl = *(const float4*)(cosp + pb);
    float4 sl = *(const float4*)(sinp + pb);
    float4 ch = *(const float4*)(cosp + pb + 36);
    float4 sh = *(const float4*)(sinp + pb + 36);

    {   // Q (scaled)
        float a0 = __half2float(Qpre[gb + 0]), a1 = __half2float(Qpre[gb + 1]);
        float a2 = __half2float(Qpre[gb + 2]), a3 = __half2float(Qpre[gb + 3]);
        float b0 = __half2float(Qpre[gb + 36]), b1 = __half2float(Qpre[gb + 37]);
        float b2 = __half2float(Qpre[gb + 38]), b3 = __half2float(Qpre[gb + 39]);
        float rl[4] = { (a0 * cl.x - b0 * sl.x) * scale, (a1 * cl.y - b1 * sl.y) * scale,
                        (a2 * cl.z - b2 * sl.z) * scale, (a3 * cl.w - b3 * sl.w) * scale };
        float rh[4] = { (b0 * ch.x + a0 * sh.x) * scale, (b1 * ch.y + a1 * sh.y) * scale,
                        (b2 * ch.z + a2 * sh.z) * scale, (b3 * ch.w + a3 * sh.w) * scale };
        *(uint2*)(Qr + gb)      = make_uint2(pk2h(rl[0], rl[1]), pk2h(rl[2], rl[3]));
        *(uint2*)(Qr + gb + 36) = make_uint2(pk2h(rh[0], rh[1]), pk2h(rh[2], rh[3]));
    }
    {   // K (unscaled)
        float a0 = __half2float(Kpre[gb + 0]), a1 = __half2float(Kpre[gb + 1]);
        float a2 = __half2float(Kpre[gb + 2]), a3 = __half2float(Kpre[gb + 3]);
        float b0 = __half2float(Kpre[gb + 36]), b1 = __half2float(Kpre[gb + 37]);
        float b2 = __half2float(Kpre[gb + 38]), b3 = __half2float(Kpre[gb + 39]);
        float rl[4] = { a0 * cl.x - b0 * sl.x, a1 * cl.y - b1 * sl.y,
                        a2 * cl.z - b2 * sl.z, a3 * cl.w - b3 * sl.w };
        float rh[4] = { b0 * ch.x + a0 * sh.x, b1 * ch.y + a1 * sh.y,
                        b2 * ch.z + a2 * sh.z, b3 * ch.w + a3 * sh.w };
        *(uint2*)(Kr + gb)      = make_uint2(pk2h(rl[0], rl[1]), pk2h(rl[2], rl[3]));
        *(uint2*)(Kr + gb + 36) = make_uint2(pk2h(rh[0], rh[1]), pk2h(rh[2], rh[3]));
    }
}

// ---------------------------------------------------------------------------
// HMMA flash attention: 64-key 2-stage pipeline, two 32-key subtiles/step.
// S fp16 1-term, PV fp16 1-term.
// ---------------------------------------------------------------------------
__global__ __launch_bounds__(256, 2) void attn_mma_kernel(
    const __half* __restrict__ Q16g,
    const __half* __restrict__ K16g, const __half* __restrict__ V16g,
    __half* __restrict__ O16,
    const int* __restrict__ cu, int nseg)
{
    extern __shared__ __align__(16) char asmem[];
    const uint32_t sb = smem_u32(asmem);

    const int tid  = threadIdx.x;
    const int lane = tid & 31;
    const int w    = tid >> 5;
    const int h    = blockIdx.y;
    const int q0   = blockIdx.x * 128;

    int segStart = 0, segEnd = S_TOK;
    for (int i = 0; i < nseg; i++) {
        int a = cu[i], b = cu[i + 1];
        if (q0 >= a && q0 < b) { segStart = a; segEnd = b; }
    }
    const int n64 = (segEnd - segStart + 63) / 64;

    // zero pad bytes (dims 72..79): Q rows + both KV stage buffers
    for (int i = tid; i < 128; i += 256) {
        *(uint4*)(asmem + AQ + i * A_ROWB + 144) = make_uint4(0, 0, 0, 0);
    }
    for (int i = tid; i < 2 * 64; i += 256) {
        const int b = i >> 6, r = i & 63;
        char* rowp = asmem + AKV0 + b * KVS + r * A_ROWB + 144;
        *(uint4*)(rowp + KO) = make_uint4(0, 0, 0, 0);
        *(uint4*)(rowp + VO) = make_uint4(0, 0, 0, 0);
    }

    // stage Q (1152 chunk-pairs; hoisted div-by-9 with carry stepping)
    {
        int r = tid / 9, c = tid - r * 9;
        for (int i = tid; i < 128 * 9; i += 256) {
            const size_t g = (size_t)(q0 + r) * EMB + h * HD + c * 8;
            CP_ASYNC16(sb + AQ + r * A_ROWB + c * 16, Q16g + g);
            r += 28; c += 4;
            if (c >= 9) { c -= 9; r += 1; }
        }
    }
    CP_COMMIT();

    auto stage_kv = [&](int tt) {
        const uint32_t dst0 = sb + AKV0 + (tt & 1) * KVS;
        const int kt = segStart + tt * 64;
        int r = tid / 9, c = tid - r * 9;
        for (int i = tid; i < 64 * 9; i += 256) {
            const int key = kt + r;
            if (key < segEnd) {
                const size_t g = (size_t)key * EMB + h * HD + c * 8;
                const uint32_t d = dst0 + r * A_ROWB + c * 16;
                CP_ASYNC16(d + KO, K16g + g);
                CP_ASYNC16(d + VO, V16g + g);
            }
            r += 28; c += 4;
            if (c >= 9) { c -= 9; r += 1; }
        }
    };

    stage_kv(0); CP_COMMIT();

    const int j  = lane >> 3;
    const int l8 = lane & 7;
    const uint32_t q_off  = (uint32_t)((16 * w + (j & 1) * 8 + l8) * A_ROWB + (j >> 1) * 16);
    const uint32_t bs_off = (uint32_t)(((j >> 1) * 8 + l8) * A_ROWB + (j & 1) * 16);
    const uint32_t v_off  = (uint32_t)(((j & 1) * 8 + l8) * A_ROWB + (j >> 1) * 16);

    const int qr = lane >> 2;
    const int lc = lane & 3;

    float acc_o[10][4];
#pragma unroll
    for (int dt = 0; dt < 10; dt++)
#pragma unroll
        for (int e = 0; e < 4; e++) acc_o[dt][e] = 0.f;
    float lsum0 = 0.f, lsum1 = 0.f;

    for (int tt = 0; tt < n64; tt++) {
        CP_WAIT(0);
        __syncthreads();
        // prefetch next 64-key tile into the other buffer (overlaps compute)
        if (tt + 1 < n64) { stage_kv(tt + 1); CP_COMMIT(); }

        const uint32_t kvb = sb + AKV0 + (tt & 1) * KVS;
        const int kt = segStart + tt * 64;

        // tail: zero rows beyond segEnd (staging skipped them)
        if (kt + 64 > segEnd) {
            int r = tid / 9, c = tid - r * 9;
            for (int i = tid; i < 64 * 9; i += 256) {
                if (kt + r >= segEnd) {
                    char* dp2 = asmem + (kvb - sb) + r * A_ROWB + c * 16;
                    *(uint4*)(dp2 + KO) = make_uint4(0, 0, 0, 0);
                    *(uint4*)(dp2 + VO) = make_uint4(0, 0, 0, 0);
                }
                r += 28; c += 4;
                if (c >= 9) { c -= 9; r += 1; }
            }
            __syncthreads();
        }

#pragma unroll
        for (int sub = 0; sub < 2; sub++) {
            const uint32_t kvs = kvb + sub * (32 * A_ROWB);
            const int ks0 = kt + sub * 32;

            // ---- S = Q K^T (fp16 1-term), 32 keys -------------------------
            float acc_s[4][4];
#pragma unroll
            for (int nt = 0; nt < 4; nt++)
#pragma unroll
                for (int e = 0; e < 4; e++) acc_s[nt][e] = 0.f;

#pragma unroll
            for (int kc = 0; kc < 5; kc++) {
                uint32_t qhr[4];
                LDSM_X4(qhr, sb + AQ + q_off + kc * 32);
#pragma unroll
                for (int np = 0; np < 2; np++) {
                    uint32_t bh[4];
                    const uint32_t bo = kvs + KO + bs_off + np * (16 * A_ROWB) + kc * 32;
                    LDSM_X4(bh, bo);
                    MMA16816H(acc_s[2 * np],     qhr, bh[0], bh[1]);
                    MMA16816H(acc_s[2 * np + 1], qhr, bh[2], bh[3]);
                }
            }

            // ---- softmax (unnormalized) + mask ----------------------------
#pragma unroll
            for (int nt = 0; nt < 4; nt++) {
                const int colb = ks0 + nt * 8 + lc * 2;
                float p0 = (colb     < segEnd) ? __expf(acc_s[nt][0]) : 0.f;
                float p1 = (colb + 1 < segEnd) ? __expf(acc_s[nt][1]) : 0.f;
                float p2 = (colb     < segEnd) ? __expf(acc_s[nt][2]) : 0.f;
                float p3 = (colb + 1 < segEnd) ? __expf(acc_s[nt][3]) : 0.f;
                lsum0 += p0 + p1;
                lsum1 += p2 + p3;
                acc_s[nt][0] = p0; acc_s[nt][1] = p1;
                acc_s[nt][2] = p2; acc_s[nt][3] = p3;
            }

            // ---- O += P V (fp16 1-term) -----------------------------------
#pragma unroll
            for (int kc = 0; kc < 2; kc++) {
                uint32_t pa[4];
                const float* s0 = acc_s[2 * kc];
                const float* s1 = acc_s[2 * kc + 1];
                pa[0] = pk2h(s0[0], s0[1]); pa[1] = pk2h(s0[2], s0[3]);
                pa[2] = pk2h(s1[0], s1[1]); pa[3] = pk2h(s1[2], s1[3]);
#pragma unroll
                for (int dp = 0; dp < 5; dp++) {
                    uint32_t vh[4];
                    const uint32_t vo = kvs + VO + v_off + kc * (16 * A_ROWB) + dp * 32;
                    LDSM_X4_T(vh, vo);
                    MMA16816H(acc_o[2 * dp],     pa, vh[0], vh[1]);
                    MMA16816H(acc_o[2 * dp + 1], pa, vh[2], vh[3]);
                }
            }
        }
    }

    // ---- epilogue: normalize, write fp16 ----------------------------------
    lsum0 += __shfl_xor_sync(0xffffffffu, lsum0, 1);
    lsum0 += __shfl_xor_sync(0xffffffffu, lsum0, 2);
    lsum1 += __shfl_xor_sync(0xffffffffu, lsum1, 1);
    lsum1 += __shfl_xor_sync(0xffffffffu, lsum1, 2);
    const float inv0 = 1.0f / lsum0;
    const float inv1 = 1.0f / lsum1;
    const int row0 = q0 + 16 * w + qr;
    const int row1 = row0 + 8;
#pragma unroll
    for (int dt = 0; dt < 9; dt++) {
        const int d = dt * 8 + lc * 2;
        *(uint32_t*)(O16 + (size_t)row0 * EMB + h * HD + d) =
            pk2h(acc_o[dt][0] * inv0, acc_o[dt][1] * inv0);
        *(uint32_t*)(O16 + (size_t)row1 * EMB + h * HD + d) =
            pk2h(acc_o[dt][2] * inv1, acc_o[dt][3] * inv1);
    }
}

// ---------------------------------------------------------------------------
extern "C" void kernel_launch(void* const* d_in, const int* in_sizes, int n_in,
                              void* d_out, int out_size)
{
    const float* hs   = (const float*)d_in[0];
    const float* qw   = (const float*)d_in[1];
    const float* qb   = (const float*)d_in[2];
    const float* kw   = (const float*)d_in[3];
    const float* kb   = (const float*)d_in[4];
    const float* vw   = (const float*)d_in[5];
    const float* vb   = (const float*)d_in[6];
    const float* ow   = (const float*)d_in[7];
    const float* ob   = (const float*)d_in[8];
    const float* cosp = (const float*)d_in[9];
    const float* sinp = (const float*)d_in[10];
    const int*   cu   = (const int*)d_in[11];
    const int nseg = in_sizes[11] - 1;

    __half *qpre, *kpre, *q16, *k16, *v16, *hs16, *a16, *w16;
    cudaGetSymbolAddress((void**)&qpre, g_qpre);
    cudaGetSymbolAddress((void**)&kpre, g_kpre);
    cudaGetSymbolAddress((void**)&q16, g_q16);
    cudaGetSymbolAddress((void**)&k16, g_k16);
    cudaGetSymbolAddress((void**)&v16, g_v16);
    cudaGetSymbolAddress((void**)&hs16, g_hs16);
    cudaGetSymbolAddress((void**)&a16, g_a16);
    cudaGetSymbolAddress((void**)&w16, g_w16);

    cudaFuncSetAttribute(qkv_f16_kernel,
                         cudaFuncAttributeMaxDynamicSharedMemorySize, PRJ_SMEM);
    cudaFuncSetAttribute(oproj_f16_kernel,
                         cudaFuncAttributeMaxDynamicSharedMemorySize, PRJ_SMEM);
    cudaFuncSetAttribute(attn_mma_kernel,
                         cudaFuncAttributeMaxDynamicSharedMemorySize, ATTN_SMEM);

    // 0) conversions: hs + 4 weights -> fp16
    cvt_all_kernel<<<(CVT_TOTAL + 255) / 256, 256>>>(
        hs, qw, kw, vw, ow, hs16, w16);

    // 1) Q/K/V projections (fp16 1-term, BN=64)
    qkv_f16_kernel<<<dim3(EMB / 64, S_TOK / 128, 3), 256, PRJ_SMEM>>>(
        hs16, w16, qb, kb, vb, qpre, kpre, v16);

    // 2) prep: RoPE + scale (fp16 in/out)
    prep_qk_kernel<<<(S_TOK * NH * 9 + 255) / 256, 256>>>(
        qpre, kpre, q16, k16, cosp, sinp);

    // 3) attention (64-key 2-stage pipeline) -> a16
    attn_mma_kernel<<<dim3(S_TOK / 128, NH), 256, ATTN_SMEM>>>(
        q16, k16, v16, a16, cu, nseg);

    // 4) O projection -> d_out
    oproj_f16_kernel<<<dim3(EMB / 64, S_TOK / 128), 256, PRJ_SMEM>>>(
        a16, w16 + 3 * (size_t)EMB * EMB, ob, (float*)d_out);
}

// round 16
// speedup vs baseline: 1.1513x; 1.0755x over previous
#include <cuda_runtime.h>
#include <cuda_bf16.h>
#include <cuda_fp16.h>
#include <cstdint>
#include <math.h>

#define S_TOK 2048
#define EMB   1152
#define NH    16
#define HD    72
#define KDIM  1152
#define BK    32
#define NCHUNK (KDIM / BK)          // 36

// ---- fused qkv3 GEMM: A once + 3 weight tiles, BM=128, BN=64, 3-stage ----
#define T3_A 0
#define T3_B 10240
#define T3_STAGE 25600              // 10240 + 3*5120
#define QKV3_SMEM (3 * T3_STAGE)    // 76800

// ---- fp16 1-term GEMM, BN=64 (oproj): 3-stage ----
#define P_A 0
#define P_B 10240
#define P_STAGE 15360
#define PRJ_SMEM (3 * P_STAGE)      // 46080

// ---- attention smem: Q fp16 + 2 KV stages of 64 keys ----
#define A_ROWB 176
#define AQ   0
#define AKV0 22528
#define KO   0
#define VO   11264
#define KVS  22528
#define ATTN_SMEM (22528 + 2 * KVS) // 67584

// ---------------- scratch ----------------------------------------------------
__device__ __align__(16) __half g_qpre[S_TOK * EMB];
__device__ __align__(16) __half g_kpre[S_TOK * EMB];
__device__ __align__(16) __half g_q16 [S_TOK * EMB];
__device__ __align__(16) __half g_k16 [S_TOK * EMB];
__device__ __align__(16) __half g_v16 [S_TOK * EMB];
__device__ __align__(16) __half g_hs16[S_TOK * EMB];
__device__ __align__(16) __half g_a16 [S_TOK * EMB];
__device__ __align__(16) __half g_w16 [4][EMB * EMB];

// ---------------- helpers ----------------------------------------------------
__device__ __forceinline__ uint32_t smem_u32(const void* p) {
    uint32_t a;
    asm("{ .reg .u64 t; cvta.to.shared.u64 t, %1; cvt.u32.u64 %0, t; }"
        : "=r"(a) : "l"(p));
    return a;
}

#define CP_ASYNC16(dst, src) \
    asm volatile("cp.async.cg.shared.global [%0], [%1], 16;" :: "r"(dst), "l"(src))
#define CP_COMMIT() asm volatile("cp.async.commit_group;" ::: "memory")
#define CP_WAIT(n)  asm volatile("cp.async.wait_group %0;" :: "n"(n) : "memory")

#define LDSM_X4(r, addr) \
    asm volatile("ldmatrix.sync.aligned.m8n8.x4.shared.b16 {%0,%1,%2,%3}, [%4];" \
        : "=r"((r)[0]), "=r"((r)[1]), "=r"((r)[2]), "=r"((r)[3]) : "r"(addr))
#define LDSM_X4_T(r, addr) \
    asm volatile("ldmatrix.sync.aligned.m8n8.x4.trans.shared.b16 {%0,%1,%2,%3}, [%4];" \
        : "=r"((r)[0]), "=r"((r)[1]), "=r"((r)[2]), "=r"((r)[3]) : "r"(addr))

#define MMA16816H(d, a, b0, b1) \
    asm volatile("mma.sync.aligned.m16n8k16.row.col.f32.f16.f16.f32 " \
        "{%0,%1,%2,%3}, {%4,%5,%6,%7}, {%8,%9}, {%0,%1,%2,%3};" \
        : "+f"((d)[0]), "+f"((d)[1]), "+f"((d)[2]), "+f"((d)[3]) \
        : "r"((a)[0]), "r"((a)[1]), "r"((a)[2]), "r"((a)[3]), "r"(b0), "r"(b1))

__device__ __forceinline__ uint32_t pk2h(float lo, float hi) {
    uint32_t r;
    asm("cvt.rn.f16x2.f32 %0, %1, %2;" : "=r"(r) : "f"(hi), "f"(lo));
    return r;
}

// ---------------------------------------------------------------------------
// Fused Q/K/V GEMM: C_z[128x64] = A @ W_z^T + b_z for z=0..2, A staged ONCE.
// BM=128, BN=64, BK=32, 3-stage. All outputs fp16. 288 CTAs (1 wave @ occ2).
// ---------------------------------------------------------------------------
__global__ __launch_bounds__(256, 2) void qkv3_f16_kernel(
    const __half* __restrict__ A,
    const __half* __restrict__ w16,
    const float* __restrict__ qb, const float* __restrict__ kb,
    const float* __restrict__ vb,
    __half* __restrict__ Qpre, __half* __restrict__ Kpre,
    __half* __restrict__ V16)
{
    extern __shared__ __align__(16) char smem[];
    const uint32_t sbase = smem_u32(smem);

    const __half* W0 = w16;
    const __half* W1 = w16 + (size_t)EMB * EMB;
    const __half* W2 = w16 + 2 * (size_t)EMB * EMB;

    const int tid  = threadIdx.x;
    const int lane = tid & 31;
    const int w    = tid >> 5;
    const int wm   = w & 3;
    const int wn   = w >> 2;
    const int rBase = blockIdx.y * 128;
    const int cBase = blockIdx.x * 64;

    const int j  = lane >> 3;
    const int l8 = lane & 7;
    const uint32_t a_lane_off =
        (uint32_t)((wm * 32 + (j & 1) * 8 + l8) * 80 + (j >> 1) * 16);
    const uint32_t b_lane_off =
        (uint32_t)((wn * 32 + (j >> 1) * 8 + l8) * 80 + (j & 1) * 16);

    float acc[3][2][4][4];
#pragma unroll
    for (int z = 0; z < 3; z++)
#pragma unroll
        for (int mt = 0; mt < 2; mt++)
#pragma unroll
            for (int nt = 0; nt < 4; nt++)
#pragma unroll
                for (int e = 0; e < 4; e++) acc[z][mt][nt][e] = 0.f;

    auto load_stage = [&](int s, int kc) {
        const uint32_t dst0 = sbase + s * T3_STAGE;
        {   // A: 128 rows x 64B, staged once
            const int r = tid >> 1, c0 = (tid & 1) * 2;
            const size_t g = (size_t)(rBase + r) * KDIM + kc + c0 * 8;
            const uint32_t d = dst0 + T3_A + r * 80 + c0 * 16;
            CP_ASYNC16(d,      A + g);
            CP_ASYNC16(d + 16, A + g + 8);
        }
        {   // B: 64 rows x 64B x 3 weights
            const int r = tid >> 2, c = tid & 3;
            const size_t g = (size_t)(cBase + r) * KDIM + kc + c * 8;
            const uint32_t d = dst0 + T3_B + r * 80 + c * 16;
            CP_ASYNC16(d,             W0 + g);
            CP_ASYNC16(d + 5120,      W1 + g);
            CP_ASYNC16(d + 10240,     W2 + g);
        }
    };

    load_stage(0, 0); CP_COMMIT();
    load_stage(1, BK); CP_COMMIT();

    for (int i = 0; i < NCHUNK; i++) {
        if (i + 1 < NCHUNK) { CP_WAIT(1); } else { CP_WAIT(0); }
        __syncthreads();
        if (i + 2 < NCHUNK) {
            load_stage((i + 2) % 3, (i + 2) * BK);
            CP_COMMIT();
        }

        const uint32_t base = sbase + (i % 3) * T3_STAGE;
#pragma unroll
        for (int ks = 0; ks < 2; ks++) {
            const uint32_t koff = ks * 32;
#pragma unroll
            for (int z = 0; z < 3; z++) {
                uint32_t bh[2][4];
#pragma unroll
                for (int p = 0; p < 2; p++)
                    LDSM_X4(bh[p], base + T3_B + z * 5120 + b_lane_off + p * 1280 + koff);
#pragma unroll
                for (int mt = 0; mt < 2; mt++) {
                    uint32_t ah[4];
                    LDSM_X4(ah, base + T3_A + a_lane_off + mt * 1280 + koff);
#pragma unroll
                    for (int nt = 0; nt < 4; nt++) {
                        const int p = nt >> 1, s2 = (nt & 1) * 2;
                        MMA16816H(acc[z][mt][nt], ah, bh[p][s2], bh[p][s2 + 1]);
                    }
                }
            }
        }
    }

    const int qr = lane >> 2;
    const int qc = (lane & 3) * 2;
    const float* biases[3] = { qb, kb, vb };
    __half* outs[3] = { Qpre, Kpre, V16 };
#pragma unroll
    for (int z = 0; z < 3; z++) {
        const float* bias = biases[z];
        __half* C16 = outs[z];
#pragma unroll
        for (int mt = 0; mt < 2; mt++) {
#pragma unroll
            for (int nt = 0; nt < 4; nt++) {
                const int row = rBase + wm * 32 + mt * 16 + qr;
                const int col = cBase + wn * 32 + nt * 8 + qc;
                const float b0 = bias[col], b1 = bias[col + 1];
                *(uint32_t*)(C16 + (size_t)row * EMB + col) =
                    pk2h(acc[z][mt][nt][0] + b0, acc[z][mt][nt][1] + b1);
                *(uint32_t*)(C16 + (size_t)(row + 8) * EMB + col) =
                    pk2h(acc[z][mt][nt][2] + b0, acc[z][mt][nt][3] + b1);
            }
        }
    }
}

// ---------------------------------------------------------------------------
// oproj: fp16 1-term GEMM, BM=128, BN=64, 3-stage (verified).
// ---------------------------------------------------------------------------
__global__ __launch_bounds__(256, 2) void oproj_f16_kernel(
    const __half* __restrict__ A, const __half* __restrict__ W,
    const float* __restrict__ bias, float* __restrict__ C)
{
    extern __shared__ __align__(16) char smem[];
    const uint32_t sbase = smem_u32(smem);

    const int tid  = threadIdx.x;
    const int lane = tid & 31;
    const int w    = tid >> 5;
    const int wm   = w & 3;
    const int wn   = w >> 2;
    const int rBase = blockIdx.y * 128;
    const int cBase = blockIdx.x * 64;

    const int j  = lane >> 3;
    const int l8 = lane & 7;
    const uint32_t a_lane_off =
        (uint32_t)((wm * 32 + (j & 1) * 8 + l8) * 80 + (j >> 1) * 16);
    const uint32_t b_lane_off =
        (uint32_t)((wn * 32 + (j >> 1) * 8 + l8) * 80 + (j & 1) * 16);

    float acc[2][4][4];
#pragma unroll
    for (int mt = 0; mt < 2; mt++)
#pragma unroll
        for (int nt = 0; nt < 4; nt++)
#pragma unroll
            for (int e = 0; e < 4; e++) acc[mt][nt][e] = 0.f;

    auto load_stage = [&](int s, int kc) {
        const uint32_t dst0 = sbase + s * P_STAGE;
        {
            const int r = tid >> 1, c0 = (tid & 1) * 2;
            const size_t g = (size_t)(rBase + r) * KDIM + kc + c0 * 8;
            const uint32_t d = dst0 + P_A + r * 80 + c0 * 16;
            CP_ASYNC16(d,      A + g);
            CP_ASYNC16(d + 16, A + g + 8);
        }
        {
            const int r = tid >> 2, c = tid & 3;
            const size_t g = (size_t)(cBase + r) * KDIM + kc + c * 8;
            CP_ASYNC16(dst0 + P_B + r * 80 + c * 16, W + g);
        }
    };

    load_stage(0, 0); CP_COMMIT();
    load_stage(1, BK); CP_COMMIT();

    for (int i = 0; i < NCHUNK; i++) {
        if (i + 1 < NCHUNK) { CP_WAIT(1); } else { CP_WAIT(0); }
        __syncthreads();
        if (i + 2 < NCHUNK) {
            load_stage((i + 2) % 3, (i + 2) * BK);
            CP_COMMIT();
        }

        const uint32_t base = sbase + (i % 3) * P_STAGE;
#pragma unroll
        for (int ks = 0; ks < 2; ks++) {
            const uint32_t koff = ks * 32;
            uint32_t bh[2][4];
#pragma unroll
            for (int p = 0; p < 2; p++)
                LDSM_X4(bh[p], base + P_B + b_lane_off + p * 1280 + koff);
#pragma unroll
            for (int mt = 0; mt < 2; mt++) {
                uint32_t ah[4];
                LDSM_X4(ah, base + P_A + a_lane_off + mt * 1280 + koff);
#pragma unroll
                for (int nt = 0; nt < 4; nt++) {
                    const int p = nt >> 1, s2 = (nt & 1) * 2;
                    MMA16816H(acc[mt][nt], ah, bh[p][s2], bh[p][s2 + 1]);
                }
            }
        }
    }

    const int qr = lane >> 2;
    const int qc = (lane & 3) * 2;
#pragma unroll
    for (int mt = 0; mt < 2; mt++) {
#pragma unroll
        for (int nt = 0; nt < 4; nt++) {
            const int row = rBase + wm * 32 + mt * 16 + qr;
            const int col = cBase + wn * 32 + nt * 8 + qc;
            const float b0 = bias[col], b1 = bias[col + 1];
            *(float2*)(C + (size_t)row * EMB + col) =
                make_float2(acc[mt][nt][0] + b0, acc[mt][nt][1] + b1);
            *(float2*)(C + (size_t)(row + 8) * EMB + col) =
                make_float2(acc[mt][nt][2] + b0, acc[mt][nt][3] + b1);
        }
    }
}

// ---------------- batched fp32 -> fp16 conversions ---------------------------
#define HS8 (S_TOK * EMB / 8)
#define W8  (EMB * EMB / 8)
#define CVT_TOTAL (HS8 + 4 * W8)

__global__ __launch_bounds__(256) void cvt_all_kernel(
    const float* __restrict__ hs, const float* __restrict__ qw,
    const float* __restrict__ kw, const float* __restrict__ vw,
    const float* __restrict__ ow,
    __half* __restrict__ hs16, __half* __restrict__ w16)
{
    int t = blockIdx.x * blockDim.x + threadIdx.x;
    if (t >= CVT_TOTAL) return;
    const float* src;
    __half* dst;
    size_t off;
    if (t < HS8) {
        src = hs; dst = hs16; off = (size_t)t * 8;
    } else {
        int r = t - HS8;
        int wsel = r / W8;
        int loc = r - wsel * W8;
        const float* ws[4] = { qw, kw, vw, ow };
        src = ws[wsel];
        dst = w16 + (size_t)wsel * EMB * EMB;
        off = (size_t)loc * 8;
    }
    const float4* s4 = (const float4*)(src + off);
    float4 a = s4[0], b = s4[1];
    float v[8] = {a.x, a.y, a.z, a.w, b.x, b.y, b.z, b.w};
    uint32_t p[4];
#pragma unroll
    for (int k = 0; k < 4; k++) p[k] = pk2h(v[2 * k], v[2 * k + 1]);
    *(uint4*)(dst + off) = make_uint4(p[0], p[1], p[2], p[3]);
}

// ---------------- prep: RoPE (+scale for Q) fp16 in/out (verified) ----------
__global__ __launch_bounds__(256) void prep_qk_kernel(
    const __half* __restrict__ Qpre, const __half* __restrict__ Kpre,
    __half* __restrict__ Qr, __half* __restrict__ Kr,
    const float* __restrict__ cosp, const float* __restrict__ sinp)
{
    int idx = blockIdx.x * blockDim.x + threadIdx.x;
    if (idx >= S_TOK * NH * 9) return;
    const int c = idx % 9;
    const int t = idx / 9;
    const int h = t % NH;
    const int s = t / NH;
    const size_t gb = (size_t)s * EMB + h * HD + c * 4;
    const size_t pb = (size_t)s * HD + c * 4;
    const float scale = rsqrtf((float)HD);

    float4 cl = *(const float4*)(cosp + pb);
    float4 sl = *(const float4*)(sinp + pb);
    float4 ch = *(const float4*)(cosp + pb + 36);
    float4 sh = *(const float4*)(sinp + pb + 36);

    {   // Q (scaled)
        float a0 = __half2float(Qpre[gb + 0]), a1 = __half2float(Qpre[gb + 1]);
        float a2 = __half2float(Qpre[gb + 2]), a3 = __half2float(Qpre[gb + 3]);
        float b0 = __half2float(Qpre[gb + 36]), b1 = __half2float(Qpre[gb + 37]);
        float b2 = __half2float(Qpre[gb + 38]), b3 = __half2float(Qpre[gb + 39]);
        float rl[4] = { (a0 * cl.x - b0 * sl.x) * scale, (a1 * cl.y - b1 * sl.y) * scale,
                        (a2 * cl.z - b2 * sl.z) * scale, (a3 * cl.w - b3 * sl.w) * scale };
        float rh[4] = { (b0 * ch.x + a0 * sh.x) * scale, (b1 * ch.y + a1 * sh.y) * scale,
                        (b2 * ch.z + a2 * sh.z) * scale, (b3 * ch.w + a3 * sh.w) * scale };
        *(uint2*)(Qr + gb)      = make_uint2(pk2h(rl[0], rl[1]), pk2h(rl[2], rl[3]));
        *(uint2*)(Qr + gb + 36) = make_uint2(pk2h(rh[0], rh[1]), pk2h(rh[2], rh[3]));
    }
    {   // K (unscaled)
        float a0 = __half2float(Kpre[gb + 0]), a1 = __half2float(Kpre[gb + 1]);
        float a2 = __half2float(Kpre[gb + 2]), a3 = __half2float(Kpre[gb + 3]);
        float b0 = __half2float(Kpre[gb + 36]), b1 = __half2float(Kpre[gb + 37]);
        float b2 = __half2float(Kpre[gb + 38]), b3 = __half2float(Kpre[gb + 39]);
        float rl[4] = { a0 * cl.x - b0 * sl.x, a1 * cl.y - b1 * sl.y,
                        a2 * cl.z - b2 * sl.z, a3 * cl.w - b3 * sl.w };
        float rh[4] = { b0 * ch.x + a0 * sh.x, b1 * ch.y + a1 * sh.y,
                        b2 * ch.z + a2 * sh.z, b3 * ch.w + a3 * sh.w };
        *(uint2*)(Kr + gb)      = make_uint2(pk2h(rl[0], rl[1]), pk2h(rl[2], rl[3]));
        *(uint2*)(Kr + gb + 36) = make_uint2(pk2h(rh[0], rh[1]), pk2h(rh[2], rh[3]));
    }
}

// ---------------------------------------------------------------------------
// HMMA flash attention (R15 structure, verified): 64-key 2-stage pipeline.
// ---------------------------------------------------------------------------
__global__ __launch_bounds__(256, 2) void attn_mma_kernel(
    const __half* __restrict__ Q16g,
    const __half* __restrict__ K16g, const __half* __restrict__ V16g,
    __half* __restrict__ O16,
    const int* __restrict__ cu, int nseg)
{
    extern __shared__ __align__(16) char asmem[];
    const uint32_t sb = smem_u32(asmem);

    const int tid  = threadIdx.x;
    const int lane = tid & 31;
    const int w    = tid >> 5;
    const int h    = blockIdx.y;
    const int q0   = blockIdx.x * 128;

    int segStart = 0, segEnd = S_TOK;
    for (int i = 0; i < nseg; i++) {
        int a = cu[i], b = cu[i + 1];
        if (q0 >= a && q0 < b) { segStart = a; segEnd = b; }
    }
    const int n64 = (segEnd - segStart + 63) / 64;

    for (int i = tid; i < 128; i += 256) {
        *(uint4*)(asmem + AQ + i * A_ROWB + 144) = make_uint4(0, 0, 0, 0);
    }
    for (int i = tid; i < 2 * 64; i += 256) {
        const int b = i >> 6, r = i & 63;
        char* rowp = asmem + AKV0 + b * KVS + r * A_ROWB + 144;
        *(uint4*)(rowp + KO) = make_uint4(0, 0, 0, 0);
        *(uint4*)(rowp + VO) = make_uint4(0, 0, 0, 0);
    }

    {
        int r = tid / 9, c = tid - r * 9;
        for (int i = tid; i < 128 * 9; i += 256) {
            const size_t g = (size_t)(q0 + r) * EMB + h * HD + c * 8;
            CP_ASYNC16(sb + AQ + r * A_ROWB + c * 16, Q16g + g);
            r += 28; c += 4;
            if (c >= 9) { c -= 9; r += 1; }
        }
    }
    CP_COMMIT();

    auto stage_kv = [&](int tt) {
        const uint32_t dst0 = sb + AKV0 + (tt & 1) * KVS;
        const int kt = segStart + tt * 64;
        int r = tid / 9, c = tid - r * 9;
        for (int i = tid; i < 64 * 9; i += 256) {
            const int key = kt + r;
            if (key < segEnd) {
                const size_t g = (size_t)key * EMB + h * HD + c * 8;
                const uint32_t d = dst0 + r * A_ROWB + c * 16;
                CP_ASYNC16(d + KO, K16g + g);
                CP_ASYNC16(d + VO, V16g + g);
            }
            r += 28; c += 4;
            if (c >= 9) { c -= 9; r += 1; }
        }
    };

    stage_kv(0); CP_COMMIT();

    const int j  = lane >> 3;
    const int l8 = lane & 7;
    const uint32_t q_off  = (uint32_t)((16 * w + (j & 1) * 8 + l8) * A_ROWB + (j >> 1) * 16);
    const uint32_t bs_off = (uint32_t)(((j >> 1) * 8 + l8) * A_ROWB + (j & 1) * 16);
    const uint32_t v_off  = (uint32_t)(((j & 1) * 8 + l8) * A_ROWB + (j >> 1) * 16);

    const int qr = lane >> 2;
    const int lc = lane & 3;

    float acc_o[10][4];
#pragma unroll
    for (int dt = 0; dt < 10; dt++)
#pragma unroll
        for (int e = 0; e < 4; e++) acc_o[dt][e] = 0.f;
    float lsum0 = 0.f, lsum1 = 0.f;

    for (int tt = 0; tt < n64; tt++) {
        CP_WAIT(0);
        __syncthreads();
        if (tt + 1 < n64) { stage_kv(tt + 1); CP_COMMIT(); }

        const uint32_t kvb = sb + AKV0 + (tt & 1) * KVS;
        const int kt = segStart + tt * 64;

        if (kt + 64 > segEnd) {
            int r = tid / 9, c = tid - r * 9;
            for (int i = tid; i < 64 * 9; i += 256) {
                if (kt + r >= segEnd) {
                    char* dp2 = asmem + (kvb - sb) + r * A_ROWB + c * 16;
                    *(uint4*)(dp2 + KO) = make_uint4(0, 0, 0, 0);
                    *(uint4*)(dp2 + VO) = make_uint4(0, 0, 0, 0);
                }
                r += 28; c += 4;
                if (c >= 9) { c -= 9; r += 1; }
            }
            __syncthreads();
        }

#pragma unroll
        for (int sub = 0; sub < 2; sub++) {
            const uint32_t kvs = kvb + sub * (32 * A_ROWB);
            const int ks0 = kt + sub * 32;

            float acc_s[4][4];
#pragma unroll
            for (int nt = 0; nt < 4; nt++)
#pragma unroll
                for (int e = 0; e < 4; e++) acc_s[nt][e] = 0.f;

#pragma unroll
            for (int kc = 0; kc < 5; kc++) {
                uint32_t qhr[4];
                LDSM_X4(qhr, sb + AQ + q_off + kc * 32);
#pragma unroll
                for (int np = 0; np < 2; np++) {
                    uint32_t bh[4];
                    const uint32_t bo = kvs + KO + bs_off + np * (16 * A_ROWB) + kc * 32;
                    LDSM_X4(bh, bo);
                    MMA16816H(acc_s[2 * np],     qhr, bh[0], bh[1]);
                    MMA16816H(acc_s[2 * np + 1], qhr, bh[2], bh[3]);
                }
            }

#pragma unroll
            for (int nt = 0; nt < 4; nt++) {
                const int colb = ks0 + nt * 8 + lc * 2;
                float p0 = (colb     < segEnd) ? __expf(acc_s[nt][0]) : 0.f;
                float p1 = (colb + 1 < segEnd) ? __expf(acc_s[nt][1]) : 0.f;
                float p2 = (colb     < segEnd) ? __expf(acc_s[nt][2]) : 0.f;
                float p3 = (colb + 1 < segEnd) ? __expf(acc_s[nt][3]) : 0.f;
                lsum0 += p0 + p1;
                lsum1 += p2 + p3;
                acc_s[nt][0] = p0; acc_s[nt][1] = p1;
                acc_s[nt][2] = p2; acc_s[nt][3] = p3;
            }

#pragma unroll
            for (int kc = 0; kc < 2; kc++) {
                uint32_t pa[4];
                const float* s0 = acc_s[2 * kc];
                const float* s1 = acc_s[2 * kc + 1];
                pa[0] = pk2h(s0[0], s0[1]); pa[1] = pk2h(s0[2], s0[3]);
                pa[2] = pk2h(s1[0], s1[1]); pa[3] = pk2h(s1[2], s1[3]);
#pragma unroll
                for (int dp = 0; dp < 5; dp++) {
                    uint32_t vh[4];
                    const uint32_t vo = kvs + VO + v_off + kc * (16 * A_ROWB) + dp * 32;
                    LDSM_X4_T(vh, vo);
                    MMA16816H(acc_o[2 * dp],     pa, vh[0], vh[1]);
                    MMA16816H(acc_o[2 * dp + 1], pa, vh[2], vh[3]);
                }
            }
        }
    }

    lsum0 += __shfl_xor_sync(0xffffffffu, lsum0, 1);
    lsum0 += __shfl_xor_sync(0xffffffffu, lsum0, 2);
    lsum1 += __shfl_xor_sync(0xffffffffu, lsum1, 1);
    lsum1 += __shfl_xor_sync(0xffffffffu, lsum1, 2);
    const float inv0 = 1.0f / lsum0;
    const float inv1 = 1.0f / lsum1;
    const int row0 = q0 + 16 * w + qr;
    const int row1 = row0 + 8;
#pragma unroll
    for (int dt = 0; dt < 9; dt++) {
        const int d = dt * 8 + lc * 2;
        *(uint32_t*)(O16 + (size_t)row0 * EMB + h * HD + d) =
            pk2h(acc_o[dt][0] * inv0, acc_o[dt][1] * inv0);
        *(uint32_t*)(O16 + (size_t)row1 * EMB + h * HD + d) =
            pk2h(acc_o[dt][2] * inv1, acc_o[dt][3] * inv1);
    }
}

// ---------------------------------------------------------------------------
extern "C" void kernel_launch(void* const* d_in, const int* in_sizes, int n_in,
                              void* d_out, int out_size)
{
    const float* hs   = (const float*)d_in[0];
    const float* qw   = (const float*)d_in[1];
    const float* qb   = (const float*)d_in[2];
    const float* kw   = (const float*)d_in[3];
    const float* kb   = (const float*)d_in[4];
    const float* vw   = (const float*)d_in[5];
    const float* vb   = (const float*)d_in[6];
    const float* ow   = (const float*)d_in[7];
    const float* ob   = (const float*)d_in[8];
    const float* cosp = (const float*)d_in[9];
    const float* sinp = (const float*)d_in[10];
    const int*   cu   = (const int*)d_in[11];
    const int nseg = in_sizes[11] - 1;

    __half *qpre, *kpre, *q16, *k16, *v16, *hs16, *a16, *w16;
    cudaGetSymbolAddress((void**)&qpre, g_qpre);
    cudaGetSymbolAddress((void**)&kpre, g_kpre);
    cudaGetSymbolAddress((void**)&q16, g_q16);
    cudaGetSymbolAddress((void**)&k16, g_k16);
    cudaGetSymbolAddress((void**)&v16, g_v16);
    cudaGetSymbolAddress((void**)&hs16, g_hs16);
    cudaGetSymbolAddress((void**)&a16, g_a16);
    cudaGetSymbolAddress((void**)&w16, g_w16);

    cudaFuncSetAttribute(qkv3_f16_kernel,
                         cudaFuncAttributeMaxDynamicSharedMemorySize, QKV3_SMEM);
    cudaFuncSetAttribute(oproj_f16_kernel,
                         cudaFuncAttributeMaxDynamicSharedMemorySize, PRJ_SMEM);
    cudaFuncSetAttribute(attn_mma_kernel,
                         cudaFuncAttributeMaxDynamicSharedMemorySize, ATTN_SMEM);

    // 0) conversions: hs + 4 weights -> fp16
    cvt_all_kernel<<<(CVT_TOTAL + 255) / 256, 256>>>(
        hs, qw, kw, vw, ow, hs16, w16);

    // 1) fused Q/K/V projections (A staged once, 288 CTAs = 1 wave)
    qkv3_f16_kernel<<<dim3(EMB / 64, S_TOK / 128), 256, QKV3_SMEM>>>(
        hs16, w16, qb, kb, vb, qpre, kpre, v16);

    // 2) prep: RoPE + scale (fp16 in/out)
    prep_qk_kernel<<<(S_TOK * NH * 9 + 255) / 256, 256>>>(
        qpre, kpre, q16, k16, cosp, sinp);

    // 3) attention -> a16
    attn_mma_kernel<<<dim3(S_TOK / 128, NH), 256, ATTN_SMEM>>>(
        q16, k16, v16, a16, cu, nseg);

    // 4) O projection -> d_out
    oproj_f16_kernel<<<dim3(EMB / 64, S_TOK / 128), 256, PRJ_SMEM>>>(
        a16, w16 + 3 * (size_t)EMB * EMB, ob, (float*)d_out);
}

// round 17
// speedup vs baseline: 1.1521x; 1.0007x over previous
#include <cuda_runtime.h>
#include <cuda_bf16.h>
#include <cuda_fp16.h>
#include <cstdint>
#include <math.h>

#define S_TOK 2048
#define EMB   1152
#define NH    16
#define HD    72
#define KDIM  1152
#define BK    32
#define NCHUNK (KDIM / BK)          // 36

// ---- fused qkv3 GEMM: A once + 3 weight tiles, BM=128, BN=64, 3-stage ----
#define T3_A 0
#define T3_B 10240
#define T3_STAGE 25600              // 10240 + 3*5120
#define QKV3_SMEM (3 * T3_STAGE)    // 76800

// ---- fp16 1-term GEMM, BN=64 (oproj): 3-stage ----
#define P_A 0
#define P_B 10240
#define P_STAGE 15360
#define PRJ_SMEM (3 * P_STAGE)      // 46080

// ---- attention smem: Q fp16 + 2 KV stages of 64 keys ----
#define A_ROWB 176
#define AQ   0
#define AKV0 22528
#define KO   0
#define VO   11264
#define KVS  22528
#define ATTN_SMEM (22528 + 2 * KVS) // 67584

// ---------------- scratch ----------------------------------------------------
__device__ __align__(16) __half g_qpre[S_TOK * EMB];
__device__ __align__(16) __half g_kpre[S_TOK * EMB];
__device__ __align__(16) __half g_q16 [S_TOK * EMB];
__device__ __align__(16) __half g_k16 [S_TOK * EMB];
__device__ __align__(16) __half g_v16 [S_TOK * EMB];
__device__ __align__(16) __half g_hs16[S_TOK * EMB];
__device__ __align__(16) __half g_a16 [S_TOK * EMB];
__device__ __align__(16) __half g_w16 [4][EMB * EMB];

// ---------------- helpers ----------------------------------------------------
__device__ __forceinline__ uint32_t smem_u32(const void* p) {
    uint32_t a;
    asm("{ .reg .u64 t; cvta.to.shared.u64 t, %1; cvt.u32.u64 %0, t; }"
        : "=r"(a) : "l"(p));
    return a;
}

#define CP_ASYNC16(dst, src) \
    asm volatile("cp.async.cg.shared.global [%0], [%1], 16;" :: "r"(dst), "l"(src))
#define CP_COMMIT() asm volatile("cp.async.commit_group;" ::: "memory")
#define CP_WAIT(n)  asm volatile("cp.async.wait_group %0;" :: "n"(n) : "memory")

#define LDSM_X4(r, addr) \
    asm volatile("ldmatrix.sync.aligned.m8n8.x4.shared.b16 {%0,%1,%2,%3}, [%4];" \
        : "=r"((r)[0]), "=r"((r)[1]), "=r"((r)[2]), "=r"((r)[3]) : "r"(addr))
#define LDSM_X4_T(r, addr) \
    asm volatile("ldmatrix.sync.aligned.m8n8.x4.trans.shared.b16 {%0,%1,%2,%3}, [%4];" \
        : "=r"((r)[0]), "=r"((r)[1]), "=r"((r)[2]), "=r"((r)[3]) : "r"(addr))

#define MMA16816H(d, a, b0, b1) \
    asm volatile("mma.sync.aligned.m16n8k16.row.col.f32.f16.f16.f32 " \
        "{%0,%1,%2,%3}, {%4,%5,%6,%7}, {%8,%9}, {%0,%1,%2,%3};" \
        : "+f"((d)[0]), "+f"((d)[1]), "+f"((d)[2]), "+f"((d)[3]) \
        : "r"((a)[0]), "r"((a)[1]), "r"((a)[2]), "r"((a)[3]), "r"(b0), "r"(b1))

__device__ __forceinline__ uint32_t pk2h(float lo, float hi) {
    uint32_t r;
    asm("cvt.rn.f16x2.f32 %0, %1, %2;" : "=r"(r) : "f"(hi), "f"(lo));
    return r;
}

// ---------------------------------------------------------------------------
// Fused Q/K/V GEMM, A-fragments hoisted across z (ldsm/ks 12 -> 8).
// BM=128, BN=64, BK=32, 3-stage. All outputs fp16. 288 CTAs.
// ---------------------------------------------------------------------------
__global__ __launch_bounds__(256, 2) void qkv3_f16_kernel(
    const __half* __restrict__ A,
    const __half* __restrict__ w16,
    const float* __restrict__ qb, const float* __restrict__ kb,
    const float* __restrict__ vb,
    __half* __restrict__ Qpre, __half* __restrict__ Kpre,
    __half* __restrict__ V16)
{
    extern __shared__ __align__(16) char smem[];
    const uint32_t sbase = smem_u32(smem);

    const __half* W0 = w16;
    const __half* W1 = w16 + (size_t)EMB * EMB;
    const __half* W2 = w16 + 2 * (size_t)EMB * EMB;

    const int tid  = threadIdx.x;
    const int lane = tid & 31;
    const int w    = tid >> 5;
    const int wm   = w & 3;
    const int wn   = w >> 2;
    const int rBase = blockIdx.y * 128;
    const int cBase = blockIdx.x * 64;

    const int j  = lane >> 3;
    const int l8 = lane & 7;
    const uint32_t a_lane_off =
        (uint32_t)((wm * 32 + (j & 1) * 8 + l8) * 80 + (j >> 1) * 16);
    const uint32_t b_lane_off =
        (uint32_t)((wn * 32 + (j >> 1) * 8 + l8) * 80 + (j & 1) * 16);

    float acc[3][2][4][4];
#pragma unroll
    for (int z = 0; z < 3; z++)
#pragma unroll
        for (int mt = 0; mt < 2; mt++)
#pragma unroll
            for (int nt = 0; nt < 4; nt++)
#pragma unroll
                for (int e = 0; e < 4; e++) acc[z][mt][nt][e] = 0.f;

    auto load_stage = [&](int s, int kc) {
        const uint32_t dst0 = sbase + s * T3_STAGE;
        {   // A: 128 rows x 64B, staged once
            const int r = tid >> 1, c0 = (tid & 1) * 2;
            const size_t g = (size_t)(rBase + r) * KDIM + kc + c0 * 8;
            const uint32_t d = dst0 + T3_A + r * 80 + c0 * 16;
            CP_ASYNC16(d,      A + g);
            CP_ASYNC16(d + 16, A + g + 8);
        }
        {   // B: 64 rows x 64B x 3 weights
            const int r = tid >> 2, c = tid & 3;
            const size_t g = (size_t)(cBase + r) * KDIM + kc + c * 8;
            const uint32_t d = dst0 + T3_B + r * 80 + c * 16;
            CP_ASYNC16(d,             W0 + g);
            CP_ASYNC16(d + 5120,      W1 + g);
            CP_ASYNC16(d + 10240,     W2 + g);
        }
    };

    load_stage(0, 0); CP_COMMIT();
    load_stage(1, BK); CP_COMMIT();

    for (int i = 0; i < NCHUNK; i++) {
        if (i + 1 < NCHUNK) { CP_WAIT(1); } else { CP_WAIT(0); }
        __syncthreads();
        if (i + 2 < NCHUNK) {
            load_stage((i + 2) % 3, (i + 2) * BK);
            CP_COMMIT();
        }

        const uint32_t base = sbase + (i % 3) * T3_STAGE;
#pragma unroll
        for (int ks = 0; ks < 2; ks++) {
            const uint32_t koff = ks * 32;
            // A fragments loaded ONCE per ks, reused across all 3 z
            uint32_t ah[2][4];
#pragma unroll
            for (int mt = 0; mt < 2; mt++)
                LDSM_X4(ah[mt], base + T3_A + a_lane_off + mt * 1280 + koff);
#pragma unroll
            for (int z = 0; z < 3; z++) {
                uint32_t bh[2][4];
#pragma unroll
                for (int p = 0; p < 2; p++)
                    LDSM_X4(bh[p], base + T3_B + z * 5120 + b_lane_off + p * 1280 + koff);
#pragma unroll
                for (int mt = 0; mt < 2; mt++) {
#pragma unroll
                    for (int nt = 0; nt < 4; nt++) {
                        const int p = nt >> 1, s2 = (nt & 1) * 2;
                        MMA16816H(acc[z][mt][nt], ah[mt], bh[p][s2], bh[p][s2 + 1]);
                    }
                }
            }
        }
    }

    const int qr = lane >> 2;
    const int qc = (lane & 3) * 2;
    const float* biases[3] = { qb, kb, vb };
    __half* outs[3] = { Qpre, Kpre, V16 };
#pragma unroll
    for (int z = 0; z < 3; z++) {
        const float* bias = biases[z];
        __half* C16 = outs[z];
#pragma unroll
        for (int mt = 0; mt < 2; mt++) {
#pragma unroll
            for (int nt = 0; nt < 4; nt++) {
                const int row = rBase + wm * 32 + mt * 16 + qr;
                const int col = cBase + wn * 32 + nt * 8 + qc;
                const float b0 = bias[col], b1 = bias[col + 1];
                *(uint32_t*)(C16 + (size_t)row * EMB + col) =
                    pk2h(acc[z][mt][nt][0] + b0, acc[z][mt][nt][1] + b1);
                *(uint32_t*)(C16 + (size_t)(row + 8) * EMB + col) =
                    pk2h(acc[z][mt][nt][2] + b0, acc[z][mt][nt][3] + b1);
            }
        }
    }
}

// ---------------------------------------------------------------------------
// oproj: fp16 1-term GEMM, BM=128, BN=64, 3-stage (verified).
// ---------------------------------------------------------------------------
__global__ __launch_bounds__(256, 2) void oproj_f16_kernel(
    const __half* __restrict__ A, const __half* __restrict__ W,
    const float* __restrict__ bias, float* __restrict__ C)
{
    extern __shared__ __align__(16) char smem[];
    const uint32_t sbase = smem_u32(smem);

    const int tid  = threadIdx.x;
    const int lane = tid & 31;
    const int w    = tid >> 5;
    const int wm   = w & 3;
    const int wn   = w >> 2;
    const int rBase = blockIdx.y * 128;
    const int cBase = blockIdx.x * 64;

    const int j  = lane >> 3;
    const int l8 = lane & 7;
    const uint32_t a_lane_off =
        (uint32_t)((wm * 32 + (j & 1) * 8 + l8) * 80 + (j >> 1) * 16);
    const uint32_t b_lane_off =
        (uint32_t)((wn * 32 + (j >> 1) * 8 + l8) * 80 + (j & 1) * 16);

    float acc[2][4][4];
#pragma unroll
    for (int mt = 0; mt < 2; mt++)
#pragma unroll
        for (int nt = 0; nt < 4; nt++)
#pragma unroll
            for (int e = 0; e < 4; e++) acc[mt][nt][e] = 0.f;

    auto load_stage = [&](int s, int kc) {
        const uint32_t dst0 = sbase + s * P_STAGE;
        {
            const int r = tid >> 1, c0 = (tid & 1) * 2;
            const size_t g = (size_t)(rBase + r) * KDIM + kc + c0 * 8;
            const uint32_t d = dst0 + P_A + r * 80 + c0 * 16;
            CP_ASYNC16(d,      A + g);
            CP_ASYNC16(d + 16, A + g + 8);
        }
        {
            const int r = tid >> 2, c = tid & 3;
            const size_t g = (size_t)(cBase + r) * KDIM + kc + c * 8;
            CP_ASYNC16(dst0 + P_B + r * 80 + c * 16, W + g);
        }
    };

    load_stage(0, 0); CP_COMMIT();
    load_stage(1, BK); CP_COMMIT();

    for (int i = 0; i < NCHUNK; i++) {
        if (i + 1 < NCHUNK) { CP_WAIT(1); } else { CP_WAIT(0); }
        __syncthreads();
        if (i + 2 < NCHUNK) {
            load_stage((i + 2) % 3, (i + 2) * BK);
            CP_COMMIT();
        }

        const uint32_t base = sbase + (i % 3) * P_STAGE;
#pragma unroll
        for (int ks = 0; ks < 2; ks++) {
            const uint32_t koff = ks * 32;
            uint32_t bh[2][4];
#pragma unroll
            for (int p = 0; p < 2; p++)
                LDSM_X4(bh[p], base + P_B + b_lane_off + p * 1280 + koff);
#pragma unroll
            for (int mt = 0; mt < 2; mt++) {
                uint32_t ah[4];
                LDSM_X4(ah, base + P_A + a_lane_off + mt * 1280 + koff);
#pragma unroll
                for (int nt = 0; nt < 4; nt++) {
                    const int p = nt >> 1, s2 = (nt & 1) * 2;
                    MMA16816H(acc[mt][nt], ah, bh[p][s2], bh[p][s2 + 1]);
                }
            }
        }
    }

    const int qr = lane >> 2;
    const int qc = (lane & 3) * 2;
#pragma unroll
    for (int mt = 0; mt < 2; mt++) {
#pragma unroll
        for (int nt = 0; nt < 4; nt++) {
            const int row = rBase + wm * 32 + mt * 16 + qr;
            const int col = cBase + wn * 32 + nt * 8 + qc;
            const float b0 = bias[col], b1 = bias[col + 1];
            *(float2*)(C + (size_t)row * EMB + col) =
                make_float2(acc[mt][nt][0] + b0, acc[mt][nt][1] + b1);
            *(float2*)(C + (size_t)(row + 8) * EMB + col) =
                make_float2(acc[mt][nt][2] + b0, acc[mt][nt][3] + b1);
        }
    }
}

// ---------------- batched fp32 -> fp16 conversions ---------------------------
#define HS8 (S_TOK * EMB / 8)
#define W8  (EMB * EMB / 8)
#define CVT_TOTAL (HS8 + 4 * W8)

__global__ __launch_bounds__(256) void cvt_all_kernel(
    const float* __restrict__ hs, const float* __restrict__ qw,
    const float* __restrict__ kw, const float* __restrict__ vw,
    const float* __restrict__ ow,
    __half* __restrict__ hs16, __half* __restrict__ w16)
{
    int t = blockIdx.x * blockDim.x + threadIdx.x;
    if (t >= CVT_TOTAL) return;
    const float* src;
    __half* dst;
    size_t off;
    if (t < HS8) {
        src = hs; dst = hs16; off = (size_t)t * 8;
    } else {
        int r = t - HS8;
        int wsel = r / W8;
        int loc = r - wsel * W8;
        const float* ws[4] = { qw, kw, vw, ow };
        src = ws[wsel];
        dst = w16 + (size_t)wsel * EMB * EMB;
        off = (size_t)loc * 8;
    }
    const float4* s4 = (const float4*)(src + off);
    float4 a = s4[0], b = s4[1];
    float v[8] = {a.x, a.y, a.z, a.w, b.x, b.y, b.z, b.w};
    uint32_t p[4];
#pragma unroll
    for (int k = 0; k < 4; k++) p[k] = pk2h(v[2 * k], v[2 * k + 1]);
    *(uint4*)(dst + off) = make_uint4(p[0], p[1], p[2], p[3]);
}

// ---------------- prep: RoPE (+scale for Q) fp16 in/out (verified) ----------
__global__ __launch_bounds__(256) void prep_qk_kernel(
    const __half* __restrict__ Qpre, const __half* __restrict__ Kpre,
    __half* __restrict__ Qr, __half* __restrict__ Kr,
    const float* __restrict__ cosp, const float* __restrict__ sinp)
{
    int idx = blockIdx.x * blockDim.x + threadIdx.x;
    if (idx >= S_TOK * NH * 9) return;
    const int c = idx % 9;
    const int t = idx / 9;
    const int h = t % NH;
    const int s = t / NH;
    const size_t gb = (size_t)s * EMB + h * HD + c * 4;
    const size_t pb = (size_t)s * HD + c * 4;
    const float scale = rsqrtf((float)HD);

    float4 cl = *(const float4*)(cosp + pb);
    float4 sl = *(const float4*)(sinp + pb);
    float4 ch = *(const float4*)(cosp + pb + 36);
    float4 sh = *(const float4*)(sinp + pb + 36);

    {   // Q (scaled)
        float a0 = __half2float(Qpre[gb + 0]), a1 = __half2float(Qpre[gb + 1]);
        float a2 = __half2float(Qpre[gb + 2]), a3 = __half2float(Qpre[gb + 3]);
        float b0 = __half2float(Qpre[gb + 36]), b1 = __half2float(Qpre[gb + 37]);
        float b2 = __half2float(Qpre[gb + 38]), b3 = __half2float(Qpre[gb + 39]);
        float rl[4] = { (a0 * cl.x - b0 * sl.x) * scale, (a1 * cl.y - b1 * sl.y) * scale,
                        (a2 * cl.z - b2 * sl.z) * scale, (a3 * cl.w - b3 * sl.w) * scale };
        float rh[4] = { (b0 * ch.x + a0 * sh.x) * scale, (b1 * ch.y + a1 * sh.y) * scale,
                        (b2 * ch.z + a2 * sh.z) * scale, (b3 * ch.w + a3 * sh.w) * scale };
        *(uint2*)(Qr + gb)      = make_uint2(pk2h(rl[0], rl[1]), pk2h(rl[2], rl[3]));
        *(uint2*)(Qr + gb + 36) = make_uint2(pk2h(rh[0], rh[1]), pk2h(rh[2], rh[3]));
    }
    {   // K (unscaled)
        float a0 = __half2float(Kpre[gb + 0]), a1 = __half2float(Kpre[gb + 1]);
        float a2 = __half2float(Kpre[gb + 2]), a3 = __half2float(Kpre[gb + 3]);
        float b0 = __half2float(Kpre[gb + 36]), b1 = __half2float(Kpre[gb + 37]);
        float b2 = __half2float(Kpre[gb + 38]), b3 = __half2float(Kpre[gb + 39]);
        float rl[4] = { a0 * cl.x - b0 * sl.x, a1 * cl.y - b1 * sl.y,
                        a2 * cl.z - b2 * sl.z, a3 * cl.w - b3 * sl.w };
        float rh[4] = { b0 * ch.x + a0 * sh.x, b1 * ch.y + a1 * sh.y,
                        b2 * ch.z + a2 * sh.z, b3 * ch.w + a3 * sh.w };
        *(uint2*)(Kr + gb)      = make_uint2(pk2h(rl[0], rl[1]), pk2h(rl[2], rl[3]));
        *(uint2*)(Kr + gb + 36) = make_uint2(pk2h(rh[0], rh[1]), pk2h(rh[2], rh[3]));
    }
}

// ---------------------------------------------------------------------------
// HMMA flash attention (verified): 64-key 2-stage pipeline.
// ---------------------------------------------------------------------------
__global__ __launch_bounds__(256, 2) void attn_mma_kernel(
    const __half* __restrict__ Q16g,
    const __half* __restrict__ K16g, const __half* __restrict__ V16g,
    __half* __restrict__ O16,
    const int* __restrict__ cu, int nseg)
{
    extern __shared__ __align__(16) char asmem[];
    const uint32_t sb = smem_u32(asmem);

    const int tid  = threadIdx.x;
    const int lane = tid & 31;
    const int w    = tid >> 5;
    const int h    = blockIdx.y;
    const int q0   = blockIdx.x * 128;

    int segStart = 0, segEnd = S_TOK;
    for (int i = 0; i < nseg; i++) {
        int a = cu[i], b = cu[i + 1];
        if (q0 >= a && q0 < b) { segStart = a; segEnd = b; }
    }
    const int n64 = (segEnd - segStart + 63) / 64;

    for (int i = tid; i < 128; i += 256) {
        *(uint4*)(asmem + AQ + i * A_ROWB + 144) = make_uint4(0, 0, 0, 0);
    }
    for (int i = tid; i < 2 * 64; i += 256) {
        const int b = i >> 6, r = i & 63;
        char* rowp = asmem + AKV0 + b * KVS + r * A_ROWB + 144;
        *(uint4*)(rowp + KO) = make_uint4(0, 0, 0, 0);
        *(uint4*)(rowp + VO) = make_uint4(0, 0, 0, 0);
    }

    {
        int r = tid / 9, c = tid - r * 9;
        for (int i = tid; i < 128 * 9; i += 256) {
            const size_t g = (size_t)(q0 + r) * EMB + h * HD + c * 8;
            CP_ASYNC16(sb + AQ + r * A_ROWB + c * 16, Q16g + g);
            r += 28; c += 4;
            if (c >= 9) { c -= 9; r += 1; }
        }
    }
    CP_COMMIT();

    auto stage_kv = [&](int tt) {
        const uint32_t dst0 = sb + AKV0 + (tt & 1) * KVS;
        const int kt = segStart + tt * 64;
        int r = tid / 9, c = tid - r * 9;
        for (int i = tid; i < 64 * 9; i += 256) {
            const int key = kt + r;
            if (key < segEnd) {
                const size_t g = (size_t)key * EMB + h * HD + c * 8;
                const uint32_t d = dst0 + r * A_ROWB + c * 16;
                CP_ASYNC16(d + KO, K16g + g);
                CP_ASYNC16(d + VO, V16g + g);
            }
            r += 28; c += 4;
            if (c >= 9) { c -= 9; r += 1; }
        }
    };

    stage_kv(0); CP_COMMIT();

    const int j  = lane >> 3;
    const int l8 = lane & 7;
    const uint32_t q_off  = (uint32_t)((16 * w + (j & 1) * 8 + l8) * A_ROWB + (j >> 1) * 16);
    const uint32_t bs_off = (uint32_t)(((j >> 1) * 8 + l8) * A_ROWB + (j & 1) * 16);
    const uint32_t v_off  = (uint32_t)(((j & 1) * 8 + l8) * A_ROWB + (j >> 1) * 16);

    const int qr = lane >> 2;
    const int lc = lane & 3;

    float acc_o[10][4];
#pragma unroll
    for (int dt = 0; dt < 10; dt++)
#pragma unroll
        for (int e = 0; e < 4; e++) acc_o[dt][e] = 0.f;
    float lsum0 = 0.f, lsum1 = 0.f;

    for (int tt = 0; tt < n64; tt++) {
        CP_WAIT(0);
        __syncthreads();
        if (tt + 1 < n64) { stage_kv(tt + 1); CP_COMMIT(); }

        const uint32_t kvb = sb + AKV0 + (tt & 1) * KVS;
        const int kt = segStart + tt * 64;

        if (kt + 64 > segEnd) {
            int r = tid / 9, c = tid - r * 9;
            for (int i = tid; i < 64 * 9; i += 256) {
                if (kt + r >= segEnd) {
                    char* dp2 = asmem + (kvb - sb) + r * A_ROWB + c * 16;
                    *(uint4*)(dp2 + KO) = make_uint4(0, 0, 0, 0);
                    *(uint4*)(dp2 + VO) = make_uint4(0, 0, 0, 0);
                }
                r += 28; c += 4;
                if (c >= 9) { c -= 9; r += 1; }
            }
            __syncthreads();
        }

#pragma unroll
        for (int sub = 0; sub < 2; sub++) {
            const uint32_t kvs = kvb + sub * (32 * A_ROWB);
            const int ks0 = kt + sub * 32;

            float acc_s[4][4];
#pragma unroll
            for (int nt = 0; nt < 4; nt++)
#pragma unroll
                for (int e = 0; e < 4; e++) acc_s[nt][e] = 0.f;

#pragma unroll
            for (int kc = 0; kc < 5; kc++) {
                uint32_t qhr[4];
                LDSM_X4(qhr, sb + AQ + q_off + kc * 32);
#pragma unroll
                for (int np = 0; np < 2; np++) {
                    uint32_t bh[4];
                    const uint32_t bo = kvs + KO + bs_off + np * (16 * A_ROWB) + kc * 32;
                    LDSM_X4(bh, bo);
                    MMA16816H(acc_s[2 * np],     qhr, bh[0], bh[1]);
                    MMA16816H(acc_s[2 * np + 1], qhr, bh[2], bh[3]);
                }
            }

#pragma unroll
            for (int nt = 0; nt < 4; nt++) {
                const int colb = ks0 + nt * 8 + lc * 2;
                float p0 = (colb     < segEnd) ? __expf(acc_s[nt][0]) : 0.f;
                float p1 = (colb + 1 < segEnd) ? __expf(acc_s[nt][1]) : 0.f;
                float p2 = (colb     < segEnd) ? __expf(acc_s[nt][2]) : 0.f;
                float p3 = (colb + 1 < segEnd) ? __expf(acc_s[nt][3]) : 0.f;
                lsum0 += p0 + p1;
                lsum1 += p2 + p3;
                acc_s[nt][0] = p0; acc_s[nt][1] = p1;
                acc_s[nt][2] = p2; acc_s[nt][3] = p3;
            }

#pragma unroll
            for (int kc = 0; kc < 2; kc++) {
                uint32_t pa[4];
                const float* s0 = acc_s[2 * kc];
                const float* s1 = acc_s[2 * kc + 1];
                pa[0] = pk2h(s0[0], s0[1]); pa[1] = pk2h(s0[2], s0[3]);
                pa[2] = pk2h(s1[0], s1[1]); pa[3] = pk2h(s1[2], s1[3]);
#pragma unroll
                for (int dp = 0; dp < 5; dp++) {
                    uint32_t vh[4];
                    const uint32_t vo = kvs + VO + v_off + kc * (16 * A_ROWB) + dp * 32;
                    LDSM_X4_T(vh, vo);
                    MMA16816H(acc_o[2 * dp],     pa, vh[0], vh[1]);
                    MMA16816H(acc_o[2 * dp + 1], pa, vh[2], vh[3]);
                }
            }
        }
    }

    lsum0 += __shfl_xor_sync(0xffffffffu, lsum0, 1);
    lsum0 += __shfl_xor_sync(0xffffffffu, lsum0, 2);
    lsum1 += __shfl_xor_sync(0xffffffffu, lsum1, 1);
    lsum1 += __shfl_xor_sync(0xffffffffu, lsum1, 2);
    const float inv0 = 1.0f / lsum0;
    const float inv1 = 1.0f / lsum1;
    const int row0 = q0 + 16 * w + qr;
    const int row1 = row0 + 8;
#pragma unroll
    for (int dt = 0; dt < 9; dt++) {
        const int d = dt * 8 + lc * 2;
        *(uint32_t*)(O16 + (size_t)row0 * EMB + h * HD + d) =
            pk2h(acc_o[dt][0] * inv0, acc_o[dt][1] * inv0);
        *(uint32_t*)(O16 + (size_t)row1 * EMB + h * HD + d) =
            pk2h(acc_o[dt][2] * inv1, acc_o[dt][3] * inv1);
    }
}

// ---------------------------------------------------------------------------
extern "C" void kernel_launch(void* const* d_in, const int* in_sizes, int n_in,
                              void* d_out, int out_size)
{
    const float* hs   = (const float*)d_in[0];
    const float* qw   = (const float*)d_in[1];
    const float* qb   = (const float*)d_in[2];
    const float* kw   = (const float*)d_in[3];
    const float* kb   = (const float*)d_in[4];
    const float* vw   = (const float*)d_in[5];
    const float* vb   = (const float*)d_in[6];
    const float* ow   = (const float*)d_in[7];
    const float* ob   = (const float*)d_in[8];
    const float* cosp = (const float*)d_in[9];
    const float* sinp = (const float*)d_in[10];
    const int*   cu   = (const int*)d_in[11];
    const int nseg = in_sizes[11] - 1;

    __half *qpre, *kpre, *q16, *k16, *v16, *hs16, *a16, *w16;
    cudaGetSymbolAddress((void**)&qpre, g_qpre);
    cudaGetSymbolAddress((void**)&kpre, g_kpre);
    cudaGetSymbolAddress((void**)&q16, g_q16);
    cudaGetSymbolAddress((void**)&k16, g_k16);
    cudaGetSymbolAddress((void**)&v16, g_v16);
    cudaGetSymbolAddress((void**)&hs16, g_hs16);
    cudaGetSymbolAddress((void**)&a16, g_a16);
    cudaGetSymbolAddress((void**)&w16, g_w16);

    cudaFuncSetAttribute(qkv3_f16_kernel,
                         cudaFuncAttributeMaxDynamicSharedMemorySize, QKV3_SMEM);
    cudaFuncSetAttribute(oproj_f16_kernel,
                         cudaFuncAttributeMaxDynamicSharedMemorySize, PRJ_SMEM);
    cudaFuncSetAttribute(attn_mma_kernel,
                         cudaFuncAttributeMaxDynamicSharedMemorySize, ATTN_SMEM);

    // 0) conversions: hs + 4 weights -> fp16
    cvt_all_kernel<<<(CVT_TOTAL + 255) / 256, 256>>>(
        hs, qw, kw, vw, ow, hs16, w16);

    // 1) fused Q/K/V projections (A staged once, A-frags hoisted across z)
    qkv3_f16_kernel<<<dim3(EMB / 64, S_TOK / 128), 256, QKV3_SMEM>>>(
        hs16, w16, qb, kb, vb, qpre, kpre, v16);

    // 2) prep: RoPE + scale (fp16 in/out)
    prep_qk_kernel<<<(S_TOK * NH * 9 + 255) / 256, 256>>>(
        qpre, kpre, q16, k16, cosp, sinp);

    // 3) attention -> a16
    attn_mma_kernel<<<dim3(S_TOK / 128, NH), 256, ATTN_SMEM>>>(
        q16, k16, v16, a16, cu, nseg);

    // 4) O projection -> d_out
    oproj_f16_kernel<<<dim3(EMB / 64, S_TOK / 128), 256, PRJ_SMEM>>>(
        a16, w16 + 3 * (size_t)EMB * EMB, ob, (float*)d_out);
}